// round 5
// baseline (speedup 1.0000x reference)
#include <cuda_runtime.h>
#include <math.h>

#define NTOK 175616   // 56*56*56
#define CDIM 96
#define NW   512
#define WN   343
#define HIDD 384

typedef unsigned long long u64;
union F4U { float4 f; ulonglong2 u; };

__device__ __forceinline__ u64 ffma2(u64 a, u64 b, u64 c) {
    u64 d; asm("fma.rn.f32x2 %0, %1, %2, %3;" : "=l"(d) : "l"(a), "l"(b), "l"(c));
    return d;
}
__device__ __forceinline__ u64 pack2(float lo, float hi) {
    u64 r; asm("mov.b64 %0, {%1, %2};" : "=l"(r) : "f"(lo), "f"(hi));
    return r;
}
__device__ __forceinline__ float2 unpack2(u64 v) {
    float2 r; asm("mov.b64 {%0, %1}, %2;" : "=f"(r.x), "=f"(r.y) : "l"(v));
    return r;
}
__device__ __forceinline__ float hadd2(u64 v) { float2 t = unpack2(v); return t.x + t.y; }

// -------------------- scratch (device globals) -------------------------------
__device__ float g_xw  [NW*WN*CDIM];
__device__ float g_qp  [NW*WN*CDIM];
__device__ float g_kp  [NW*WN*CDIM];
__device__ float g_vp  [NW*WN*CDIM];
__device__ float g_q   [NW*WN*CDIM];
__device__ float g_k   [NW*WN*CDIM];
__device__ float g_v   [NW*WN*CDIM];
__device__ float g_ot  [NW*WN*CDIM];   // attention out, axis-mixed: flat = c*343 + n
__device__ float g_xres[NTOK*CDIM];
__device__ float g_ln2 [NTOK*CDIM];
__device__ float g_h   [NTOK*HIDD];
__device__ float g_wqkv[3*CDIM*CDIM];
__device__ float g_bqkv[3*CDIM];

// -------------------- pack qkv weights ---------------------------------------
__global__ void k_prep(const float* __restrict__ wq, const float* __restrict__ bq,
                       const float* __restrict__ wk, const float* __restrict__ bk,
                       const float* __restrict__ wv, const float* __restrict__ bv) {
    int i = blockIdx.x * 256 + threadIdx.x;
    if (i < 3*CDIM*CDIM) {
        int t = i / (CDIM*CDIM), r = i % (CDIM*CDIM);
        g_wqkv[i] = (t == 0) ? wq[r] : (t == 1) ? wk[r] : wv[r];
    }
    if (i < 3*CDIM) {
        int t = i / CDIM, r = i % CDIM;
        g_bqkv[i] = (t == 0) ? bq[r] : (t == 1) ? bk[r] : bv[r];
    }
}

// -------------------- LN1 + roll(-3) + window partition (coalesced) ----------
__global__ __launch_bounds__(256)
void k_ln1(const float* __restrict__ x,
           const float* __restrict__ gg, const float* __restrict__ bb) {
    __shared__ float xs[64*101];
    int p0 = blockIdx.x * 64;
    int tid = threadIdx.x, lane = tid & 31, wp = tid >> 5;
    for (int e = tid; e < 96*64; e += 256) {
        int c = e >> 6, i = e & 63;
        xs[i*101 + c] = x[(size_t)c*NTOK + p0 + i];
    }
    __syncthreads();
    #pragma unroll
    for (int ii = wp; ii < 64; ii += 8) {
        int p = p0 + ii;
        int s = p / 3136, r = p % 3136, h = r / 56, w = r % 56;
        int s2 = (s >= 3) ? s - 3 : s + 53;
        int h2 = (h >= 3) ? h - 3 : h + 53;
        int w2 = (w >= 3) ? w - 3 : w + 53;
        int win = (s2/7)*64 + (h2/7)*8 + (w2/7);
        int t   = (s2%7)*49 + (h2%7)*7 + (w2%7);
        float v0 = xs[ii*101 + lane];
        float v1 = xs[ii*101 + lane + 32];
        float v2 = xs[ii*101 + lane + 64];
        float sum = v0 + v1 + v2, sq = v0*v0 + v1*v1 + v2*v2;
        #pragma unroll
        for (int o = 16; o; o >>= 1) {
            sum += __shfl_xor_sync(0xffffffffu, sum, o);
            sq  += __shfl_xor_sync(0xffffffffu, sq, o);
        }
        float mean = sum * (1.f/96.f);
        float var  = sq * (1.f/96.f) - mean*mean;
        float inv  = rsqrtf(var + 1e-5f);
        float* ob = g_xw + ((size_t)win*WN + t)*CDIM;
        ob[lane]      = (v0 - mean)*inv*gg[lane]      + bb[lane];
        ob[lane + 32] = (v1 - mean)*inv*gg[lane + 32] + bb[lane + 32];
        ob[lane + 64] = (v2 - mean)*inv*gg[lane + 64] + bb[lane + 64];
    }
}

// -------------------- tiled GEMM, 96-deep K stage (packed f32x2 core) --------
// EPI: 1 GELU, 2 residual + transposed store, 3 qkv split
template<int EPI>
__global__ __launch_bounds__(256)
void k_gemm(const float* __restrict__ A, const float* __restrict__ W,
            const float* __restrict__ bias, int M, int Nout, int K,
            float* __restrict__ O0, float* __restrict__ O1, float* __restrict__ O2,
            const float* __restrict__ Res, float* __restrict__ OutT) {
    extern __shared__ float sm[];
    float* As = sm;            // 96 x 132  [k][row]
    float* Bs = sm + 96*132;   // 96 x 98   [k][col]
    int bm = blockIdx.x * 128;
    int bn = blockIdx.y * 96;
    int tid = threadIdx.x, tx = tid & 15, ty = tid >> 4;
    int lrow = tid >> 3, lk = (tid & 7) * 4;
    u64 acc2[4][6] = {};   // row-pairs x 6 cols

    for (int k0 = 0; k0 < K; k0 += 96) {
        #pragma unroll
        for (int i = 0; i < 4; i++) {
            int r = lrow + i*32;
            #pragma unroll
            for (int j = 0; j < 3; j++) {
                int k = lk + j*32;
                float4 v = *(const float4*)(A + (size_t)(bm + r)*K + k0 + k);
                As[(k+0)*132 + r] = v.x;
                As[(k+1)*132 + r] = v.y;
                As[(k+2)*132 + r] = v.z;
                As[(k+3)*132 + r] = v.w;
            }
        }
        #pragma unroll
        for (int i = 0; i < 3; i++) {
            int c = lrow + i*32;
            #pragma unroll
            for (int j = 0; j < 3; j++) {
                int k = lk + j*32;
                float4 v = *(const float4*)(W + (size_t)(bn + c)*K + k0 + k);
                Bs[(k+0)*98 + c] = v.x;
                Bs[(k+1)*98 + c] = v.y;
                Bs[(k+2)*98 + c] = v.z;
                Bs[(k+3)*98 + c] = v.w;
            }
        }
        __syncthreads();
        #pragma unroll 8
        for (int kk = 0; kk < 96; kk++) {
            F4U A0, A1;
            A0.f = *(const float4*)(As + kk*132 + ty*8);
            A1.f = *(const float4*)(As + kk*132 + ty*8 + 4);
            float2 b0 = *(const float2*)(Bs + kk*98 + tx*6);
            float2 b1 = *(const float2*)(Bs + kk*98 + tx*6 + 2);
            float2 b2 = *(const float2*)(Bs + kk*98 + tx*6 + 4);
            u64 aa[4] = {A0.u.x, A0.u.y, A1.u.x, A1.u.y};
            u64 bb[6] = {pack2(b0.x,b0.x), pack2(b0.y,b0.y),
                         pack2(b1.x,b1.x), pack2(b1.y,b1.y),
                         pack2(b2.x,b2.x), pack2(b2.y,b2.y)};
            #pragma unroll
            for (int i = 0; i < 4; i++)
                #pragma unroll
                for (int j = 0; j < 6; j++)
                    acc2[i][j] = ffma2(aa[i], bb[j], acc2[i][j]);
        }
        __syncthreads();
    }

    float acc[8][6];
    #pragma unroll
    for (int i2 = 0; i2 < 4; i2++)
        #pragma unroll
        for (int j = 0; j < 6; j++) {
            float2 t = unpack2(acc2[i2][j]);
            acc[2*i2][j] = t.x;
            acc[2*i2+1][j] = t.y;
        }

    if (EPI == 3) {
        float* o = (blockIdx.y == 0) ? O0 : (blockIdx.y == 1) ? O1 : O2;
        #pragma unroll
        for (int i = 0; i < 8; i++) {
            int row = bm + ty*8 + i;
            #pragma unroll
            for (int j = 0; j < 6; j++) {
                int col = tx*6 + j;
                o[(size_t)row*96 + col] = acc[i][j] + bias[bn + col];
            }
        }
    } else if (EPI == 1) {
        #pragma unroll
        for (int i = 0; i < 8; i++) {
            int row = bm + ty*8 + i;
            #pragma unroll
            for (int j = 0; j < 6; j++) {
                int col = bn + tx*6 + j;
                float v = acc[i][j] + bias[col];
                v = 0.5f * v * (1.f + erff(v * 0.70710678118654752f));
                O0[(size_t)row*Nout + col] = v;
            }
        }
    } else if (EPI == 2) {
        float* st = sm;
        for (int c0 = 0; c0 < 96; c0 += 48) {
            if ((tx < 8) == (c0 == 0)) {
                #pragma unroll
                for (int i = 0; i < 8; i++) {
                    int row = ty*8 + i;
                    #pragma unroll
                    for (int j = 0; j < 6; j++) {
                        int col = tx*6 + j;
                        float v = acc[i][j] + bias[col] + Res[(size_t)(bm + row)*96 + col];
                        st[(col - c0)*132 + row] = v;
                    }
                }
            }
            __syncthreads();
            for (int e = tid; e < 48*128; e += 256) {
                int col = e >> 7, r = e & 127;
                OutT[(size_t)(c0 + col)*NTOK + bm + r] = st[col*132 + r];
            }
            __syncthreads();
        }
    }
}

// -------------------- depthwise 3x3x3 (packed) --------------------------------
__global__ __launch_bounds__(392, 2)
void k_dw(const float* __restrict__ In, const float* __restrict__ Wt,
          const float* __restrict__ Bi, float* __restrict__ Ot) {
    __shared__ float sin_[WN*32];
    __shared__ float wsm[27*32];
    int win = blockIdx.x;
    int c0 = blockIdx.y * 32;
    int tid = threadIdx.x;
    const float* inw = In + (size_t)win*WN*CDIM + c0;
    for (int e = tid; e < WN*8; e += 392) {
        int t = e >> 3, c4 = e & 7;
        *(float4*)(sin_ + t*32 + c4*4) = *(const float4*)(inw + t*96 + c4*4);
    }
    for (int e = tid; e < 27*32; e += 392) {
        int k = e >> 5, cc = e & 31;
        wsm[k*32 + cc] = Wt[(c0 + cc)*27 + k];
    }
    __syncthreads();

    int g = tid & 7, dy = (tid >> 3) % 7, dz = tid / 56;
    int cc = g * 4;
    F4U bias4; bias4.f = *(const float4*)(Bi + c0 + cc);
    u64 ax[7], ay[7];
    #pragma unroll
    for (int x = 0; x < 7; x++) { ax[x] = bias4.u.x; ay[x] = bias4.u.y; }

    #pragma unroll
    for (int kd = 0; kd < 3; kd++) {
        int nz = dz + kd - 1;
        if ((unsigned)nz >= 7u) continue;
        #pragma unroll
        for (int kh = 0; kh < 3; kh++) {
            int ny = dy + kh - 1;
            if ((unsigned)ny >= 7u) continue;
            const float* row = sin_ + (nz*49 + ny*7)*32 + cc;
            F4U iv[7];
            #pragma unroll
            for (int x = 0; x < 7; x++) iv[x].f = *(const float4*)(row + x*32);
            const float* wp_ = wsm + (kd*9 + kh*3)*32 + cc;
            F4U w0, w1, w2;
            w0.f = *(const float4*)(wp_);
            w1.f = *(const float4*)(wp_ + 32);
            w2.f = *(const float4*)(wp_ + 64);
            #pragma unroll
            for (int x = 1; x < 7; x++) {
                ax[x] = ffma2(w0.u.x, iv[x-1].u.x, ax[x]);
                ay[x] = ffma2(w0.u.y, iv[x-1].u.y, ay[x]);
            }
            #pragma unroll
            for (int x = 0; x < 7; x++) {
                ax[x] = ffma2(w1.u.x, iv[x].u.x, ax[x]);
                ay[x] = ffma2(w1.u.y, iv[x].u.y, ay[x]);
            }
            #pragma unroll
            for (int x = 0; x < 6; x++) {
                ax[x] = ffma2(w2.u.x, iv[x+1].u.x, ax[x]);
                ay[x] = ffma2(w2.u.y, iv[x+1].u.y, ay[x]);
            }
        }
    }

    float* outw = Ot + (size_t)win*WN*CDIM + (dz*49 + dy*7)*96 + c0 + cc;
    #pragma unroll
    for (int x = 0; x < 7; x++) {
        F4U o; o.u.x = ax[x]; o.u.y = ay[x];
        *(float4*)(outw + x*96) = o.f;
    }
}

// -------------------- fused attention helper: 4 q x JN key-cols --------------
template<int JB, int JN>
__device__ __forceinline__ void qk_dot(const float* __restrict__ ks,
                                       const float* __restrict__ myq,  // stride 344/qi
                                       int lane, float sc[4][11]) {
    u64 acc2[4][JN];
    #pragma unroll
    for (int qi = 0; qi < 4; qi++)
        #pragma unroll
        for (int jj = 0; jj < JN; jj++) acc2[qi][jj] = 0ull;

    #pragma unroll 4
    for (int c4 = 0; c4 < 24; c4++) {
        F4U qv0, qv1, qv2, qv3;
        qv0.f = *(const float4*)(myq + 0*344 + c4*4);
        qv1.f = *(const float4*)(myq + 1*344 + c4*4);
        qv2.f = *(const float4*)(myq + 2*344 + c4*4);
        qv3.f = *(const float4*)(myq + 3*344 + c4*4);
        #pragma unroll
        for (int jj = 0; jj < JN; jj++) {
            F4U kv;
            kv.f = *(const float4*)(ks + (lane + 32*(JB + jj))*100 + c4*4);
            acc2[0][jj] = ffma2(kv.u.x, qv0.u.x, acc2[0][jj]);
            acc2[0][jj] = ffma2(kv.u.y, qv0.u.y, acc2[0][jj]);
            acc2[1][jj] = ffma2(kv.u.x, qv1.u.x, acc2[1][jj]);
            acc2[1][jj] = ffma2(kv.u.y, qv1.u.y, acc2[1][jj]);
            acc2[2][jj] = ffma2(kv.u.x, qv2.u.x, acc2[2][jj]);
            acc2[2][jj] = ffma2(kv.u.y, qv2.u.y, acc2[2][jj]);
            acc2[3][jj] = ffma2(kv.u.x, qv3.u.x, acc2[3][jj]);
            acc2[3][jj] = ffma2(kv.u.y, qv3.u.y, acc2[3][jj]);
        }
    }
    #pragma unroll
    for (int qi = 0; qi < 4; qi++)
        #pragma unroll
        for (int jj = 0; jj < JN; jj++)
            sc[qi][JB + jj] = hadd2(acc2[qi][jj]);
}

// -------------------- fused attention: QK^T + mask + softmax + PV ------------
// One block per window, 512 threads. 6 q-chunks of 64 (warp w -> 4 q rows).
// smem: kv[352*100] holds K (phase A) then V (phase B); pbuf[64][344] holds
// staged q then P then transposed O for the chunk.
__global__ __launch_bounds__(512)
void k_attn(const float* __restrict__ Q, const float* __restrict__ Km,
            const float* __restrict__ Vm) {
    extern __shared__ float sm[];
    float* kv   = sm;            // 352*100
    float* pbuf = sm + 352*100;  // 64*344
    int win = blockIdx.x;
    int tid = threadIdx.x, lane = tid & 31, wp = tid >> 5;
    const float* kw = Km + (size_t)win*WN*CDIM;
    const float* vw = Vm + (size_t)win*WN*CDIM;
    const float* qw = Q  + (size_t)win*WN*CDIM;
    float* ob = g_ot + (size_t)win*WN*CDIM;

    int ws = win >> 6, hs = (win >> 3) & 7, wd = win & 7;
    bool bz = (ws == 7), bh = (hs == 7), bw = (wd == 7);
    const float scale = 0.10206207261596575f; // 1/sqrt(96)

    unsigned mzm = 0, mhm = 0, mwm = 0, mvm = 0;
    #pragma unroll
    for (int j = 0; j < 11; j++) {
        int m = lane + 32*j;
        if (m < WN) {
            int dzm = m / 49, rm = m % 49, dym = rm / 7, dxm = rm % 7;
            if (dzm < 4) mzm |= 1u << j;
            if (dym < 4) mhm |= 1u << j;
            if (dxm < 4) mwm |= 1u << j;
            mvm |= 1u << j;
        }
    }

    float* myrows = pbuf + wp*4*344;

    for (int chunk = 0; chunk < 6; chunk++) {
        int qbase = chunk*64 + wp*4;
        __syncthreads();   // previous chunk fully done before kv overwrite
        for (int e = tid; e < WN*CDIM; e += 512)
            kv[(e/96)*100 + (e%96)] = kw[e];
        __syncthreads();

        // ---- phase A: stage q, scores, mask, softmax, P -> pbuf ----
        #pragma unroll
        for (int qi = 0; qi < 4; qi++) {
            int q = qbase + qi;
            if (q < WN) {
                myrows[qi*344 + lane]      = qw[q*96 + lane]      * scale;
                myrows[qi*344 + lane + 32] = qw[q*96 + lane + 32] * scale;
                myrows[qi*344 + lane + 64] = qw[q*96 + lane + 64] * scale;
            }
        }
        __syncwarp();
        float sc[4][11];
        qk_dot<0, 6>(kv, myrows, lane, sc);
        qk_dot<6, 5>(kv, myrows, lane, sc);
        __syncwarp();
        #pragma unroll
        for (int qi = 0; qi < 4; qi++) {
            int q = qbase + qi;
            if (q >= WN) break;
            int dzq = q / 49, rq = q % 49, dyq = rq / 7, dxq = rq % 7;
            bool gz = dzq < 4, gh = dyq < 4, gw = dxq < 4;
            float mx = -1e30f;
            #pragma unroll
            for (int j = 0; j < 11; j++) {
                float v;
                if (mvm & (1u << j)) {
                    bool same = (!bz || (gz == ((mzm >> j) & 1))) &&
                                (!bh || (gh == ((mhm >> j) & 1))) &&
                                (!bw || (gw == ((mwm >> j) & 1)));
                    v = sc[qi][j] + (same ? 0.f : -100.f);
                } else v = -1e30f;
                sc[qi][j] = v;
                mx = fmaxf(mx, v);
            }
            #pragma unroll
            for (int o = 16; o; o >>= 1) mx = fmaxf(mx, __shfl_xor_sync(0xffffffffu, mx, o));
            float ssum = 0.f;
            #pragma unroll
            for (int j = 0; j < 11; j++) { sc[qi][j] = __expf(sc[qi][j] - mx); ssum += sc[qi][j]; }
            #pragma unroll
            for (int o = 16; o; o >>= 1) ssum += __shfl_xor_sync(0xffffffffu, ssum, o);
            float rinv = 1.f / ssum;
            #pragma unroll
            for (int j = 0; j < 11; j++) {
                int m = lane + 32*j;
                if (m < WN) myrows[qi*344 + m] = sc[qi][j] * rinv;
            }
        }
        if (lane < 4) myrows[lane*344 + 343] = 0.f;   // pad for m-pair packing
        __syncthreads();   // all P written, all K reads done

        // ---- swap kv to V (+ zero pad rows for pair at m=343) ----
        for (int e = tid; e < WN*CDIM; e += 512)
            kv[(e/96)*100 + (e%96)] = vw[e];
        for (int e = tid; e < 9*100; e += 512)
            kv[343*100 + e] = 0.f;
        __syncthreads();

        // ---- phase B: O = P @ V (m-pair packed) ----
        u64 acc2[4][3] = {};
        #pragma unroll 2
        for (int mi = 0; mi < 344; mi += 2) {
            u64 v0 = pack2(kv[mi*100 + lane],      kv[mi*100 + 100 + lane]);
            u64 v1 = pack2(kv[mi*100 + lane + 32], kv[mi*100 + 132 + lane]);
            u64 v2 = pack2(kv[mi*100 + lane + 64], kv[mi*100 + 164 + lane]);
            #pragma unroll
            for (int qi = 0; qi < 4; qi++) {
                u64 pp = *(const u64*)(myrows + qi*344 + mi);
                acc2[qi][0] = ffma2(pp, v0, acc2[qi][0]);
                acc2[qi][1] = ffma2(pp, v1, acc2[qi][1]);
                acc2[qi][2] = ffma2(pp, v2, acc2[qi][2]);
            }
        }
        // ---- transpose-stage O into own rows, then store axis-mixed ----
        #pragma unroll
        for (int qi = 0; qi < 4; qi++) {
            myrows[ lane      *4 + qi] = hadd2(acc2[qi][0]);
            myrows[(lane + 32)*4 + qi] = hadd2(acc2[qi][1]);
            myrows[(lane + 64)*4 + qi] = hadd2(acc2[qi][2]);
        }
        __syncwarp();
        #pragma unroll
        for (int e = lane; e < 384; e += 32) {
            int c = e >> 2, qi = e & 3;
            int q = qbase + qi;
            if (q < WN) ob[(size_t)c*WN + q] = myrows[e];
        }
        // trailing __syncthreads at top of next chunk protects kv/pbuf
    }
}

// -------------------- window-reverse + roll(+3) + residual + LN2 (fused) -----
__global__ __launch_bounds__(256)
void k_resln2(const float* __restrict__ x,
              const float* __restrict__ gg, const float* __restrict__ bb) {
    __shared__ float xs[32*101];
    int p0 = blockIdx.x * 32;
    int tid = threadIdx.x, lane = tid & 31, wp = tid >> 5;
    for (int e = tid; e < 96*32; e += 256) {
        int c = e >> 5, i = e & 31;
        xs[i*101 + c] = x[(size_t)c*NTOK + p0 + i];
    }
    __syncthreads();
    #pragma unroll
    for (int ii = wp; ii < 32; ii += 8) {
        int p = p0 + ii;
        int s = p / 3136, r = p % 3136, h = r / 56, w = r % 56;
        int s2 = (s >= 3) ? s - 3 : s + 53;
        int h2 = (h >= 3) ? h - 3 : h + 53;
        int w2 = (w >= 3) ? w - 3 : w + 53;
        int win = (s2/7)*64 + (h2/7)*8 + (w2/7);
        int np  = (s2%7)*49 + (h2%7)*7 + (w2%7);
        const float* ov = g_ot + (size_t)win*WN*CDIM + np*96;
        float v0 = xs[ii*101 + lane]      + ov[lane];
        float v1 = xs[ii*101 + lane + 32] + ov[lane + 32];
        float v2 = xs[ii*101 + lane + 64] + ov[lane + 64];
        float* xr = g_xres + (size_t)p*CDIM;
        xr[lane] = v0; xr[lane + 32] = v1; xr[lane + 64] = v2;
        float sum = v0 + v1 + v2, sq = v0*v0 + v1*v1 + v2*v2;
        #pragma unroll
        for (int o = 16; o; o >>= 1) {
            sum += __shfl_xor_sync(0xffffffffu, sum, o);
            sq  += __shfl_xor_sync(0xffffffffu, sq, o);
        }
        float mean = sum * (1.f/96.f);
        float var  = sq * (1.f/96.f) - mean*mean;
        float inv  = rsqrtf(var + 1e-5f);
        float* yo = g_ln2 + (size_t)p*CDIM;
        yo[lane]      = (v0 - mean)*inv*gg[lane]      + bb[lane];
        yo[lane + 32] = (v1 - mean)*inv*gg[lane + 32] + bb[lane + 32];
        yo[lane + 64] = (v2 - mean)*inv*gg[lane + 64] + bb[lane + 64];
    }
}

// -------------------- launch --------------------------------------------------
extern "C" void kernel_launch(void* const* d_in, const int* in_sizes, int n_in,
                              void* d_out, int out_size) {
    const float* x   = (const float*)d_in[0];
    const float* n1g = (const float*)d_in[1];
    const float* n1b = (const float*)d_in[2];
    const float* wq  = (const float*)d_in[3];
    const float* bq  = (const float*)d_in[4];
    const float* wk  = (const float*)d_in[5];
    const float* bk  = (const float*)d_in[6];
    const float* wv  = (const float*)d_in[7];
    const float* bv  = (const float*)d_in[8];
    const float* dqw = (const float*)d_in[9];
    const float* dqb = (const float*)d_in[10];
    const float* dkw = (const float*)d_in[11];
    const float* dkb = (const float*)d_in[12];
    const float* dvw = (const float*)d_in[13];
    const float* dvb = (const float*)d_in[14];
    const float* n2g = (const float*)d_in[15];
    const float* n2b = (const float*)d_in[16];
    const float* f1w = (const float*)d_in[17];
    const float* f1b = (const float*)d_in[18];
    const float* f2w = (const float*)d_in[19];
    const float* f2b = (const float*)d_in[20];
    float* out = (float*)d_out;

    float *pxw, *pqp, *pkp, *pvp, *pq, *pk, *pv, *pln2, *ph, *pxres, *pwqkv, *pbqkv;
    cudaGetSymbolAddress((void**)&pxw,   g_xw);
    cudaGetSymbolAddress((void**)&pqp,   g_qp);
    cudaGetSymbolAddress((void**)&pkp,   g_kp);
    cudaGetSymbolAddress((void**)&pvp,   g_vp);
    cudaGetSymbolAddress((void**)&pq,    g_q);
    cudaGetSymbolAddress((void**)&pk,    g_k);
    cudaGetSymbolAddress((void**)&pv,    g_v);
    cudaGetSymbolAddress((void**)&pln2,  g_ln2);
    cudaGetSymbolAddress((void**)&ph,    g_h);
    cudaGetSymbolAddress((void**)&pxres, g_xres);
    cudaGetSymbolAddress((void**)&pwqkv, g_wqkv);
    cudaGetSymbolAddress((void**)&pbqkv, g_bqkv);

    const int GEMM_SMEM = (96*132 + 96*98) * 4;            // 88320 B
    const int ATTN_SMEM = (352*100 + 64*344) * 4;          // 228864 B
    cudaFuncSetAttribute(k_gemm<1>, cudaFuncAttributeMaxDynamicSharedMemorySize, GEMM_SMEM);
    cudaFuncSetAttribute(k_gemm<2>, cudaFuncAttributeMaxDynamicSharedMemorySize, GEMM_SMEM);
    cudaFuncSetAttribute(k_gemm<3>, cudaFuncAttributeMaxDynamicSharedMemorySize, GEMM_SMEM);
    cudaFuncSetAttribute(k_attn,    cudaFuncAttributeMaxDynamicSharedMemorySize, ATTN_SMEM);

    k_prep<<<(3*CDIM*CDIM + 255)/256, 256>>>(wq, bq, wk, bk, wv, bv);
    k_ln1<<<NTOK/64, 256>>>(x, n1g, n1b);

    dim3 gq(NTOK/128, 3);
    k_gemm<3><<<gq, 256, GEMM_SMEM>>>(pxw, pwqkv, pbqkv, NTOK, 288, 96,
                                      pqp, pkp, pvp, nullptr, nullptr);

    dim3 gdw(NW, 3);
    k_dw<<<gdw, 392>>>(pqp, dqw, dqb, pq);
    k_dw<<<gdw, 392>>>(pkp, dkw, dkb, pk);
    k_dw<<<gdw, 392>>>(pvp, dvw, dvb, pv);

    k_attn<<<NW, 512, ATTN_SMEM>>>(pq, pk, pv);

    k_resln2<<<NTOK/32, 256>>>(x, n2g, n2b);

    dim3 g2(NTOK/128, HIDD/96);
    k_gemm<1><<<g2, 256, GEMM_SMEM>>>(pln2, f1w, f1b, NTOK, HIDD, 96,
                                      ph, nullptr, nullptr, nullptr, nullptr);
    dim3 g3(NTOK/128, 1);
    k_gemm<2><<<g3, 256, GEMM_SMEM>>>(ph, f2w, f2b, NTOK, 96, HIDD,
                                      nullptr, nullptr, nullptr, pxres, out);
}

// round 7
// speedup vs baseline: 1.0422x; 1.0422x over previous
#include <cuda_runtime.h>
#include <cuda_bf16.h>
#include <math.h>
#include <stdint.h>

#define NTOK 175616   // 56*56*56
#define CDIM 96
#define NW   512
#define WN   343
#define HIDD 384

typedef unsigned long long u64;
typedef unsigned int u32;
union F4U { float4 f; ulonglong2 u; };

__device__ __forceinline__ u64 ffma2(u64 a, u64 b, u64 c) {
    u64 d; asm("fma.rn.f32x2 %0, %1, %2, %3;" : "=l"(d) : "l"(a), "l"(b), "l"(c));
    return d;
}
__device__ __forceinline__ u64 pack2(float lo, float hi) {
    u64 r; asm("mov.b64 %0, {%1, %2};" : "=l"(r) : "f"(lo), "f"(hi));
    return r;
}
__device__ __forceinline__ float2 unpack2(u64 v) {
    float2 r; asm("mov.b64 {%0, %1}, %2;" : "=f"(r.x), "=f"(r.y) : "l"(v));
    return r;
}
__device__ __forceinline__ float hadd2(u64 v) { float2 t = unpack2(v); return t.x + t.y; }

__device__ __forceinline__ void bsplit(float v, __nv_bfloat16& h, __nv_bfloat16& l) {
    h = __float2bfloat16_rn(v);
    l = __float2bfloat16_rn(v - __bfloat162float(h));
}
__device__ __forceinline__ u32 pack_bf(__nv_bfloat16 a, __nv_bfloat16 b) {
    return (u32)__bfloat16_as_ushort(a) | ((u32)__bfloat16_as_ushort(b) << 16);
}
__device__ __forceinline__ float gelu_f(float v) {
    return 0.5f * v * (1.f + erff(v * 0.70710678118654752f));
}
__device__ __forceinline__ void mma16816(float* d, u32 a0, u32 a1, u32 a2, u32 a3,
                                         u32 b0, u32 b1) {
    asm volatile("mma.sync.aligned.m16n8k16.row.col.f32.bf16.bf16.f32 "
                 "{%0,%1,%2,%3}, {%4,%5,%6,%7}, {%8,%9}, {%0,%1,%2,%3};"
                 : "+f"(d[0]), "+f"(d[1]), "+f"(d[2]), "+f"(d[3])
                 : "r"(a0), "r"(a1), "r"(a2), "r"(a3), "r"(b0), "r"(b1));
}

// -------------------- scratch (device globals) -------------------------------
__device__ __nv_bfloat16 g_xwh[(size_t)NTOK*CDIM], g_xwl[(size_t)NTOK*CDIM];
__device__ float g_qp [(size_t)NTOK*CDIM];
__device__ float g_kp [(size_t)NTOK*CDIM];
__device__ float g_vp [(size_t)NTOK*CDIM];
__device__ float g_q  [(size_t)NTOK*CDIM];
__device__ float g_k  [(size_t)NTOK*CDIM];
__device__ float g_v  [(size_t)NTOK*CDIM];
__device__ float g_ot [(size_t)NTOK*CDIM];   // attention out, axis-mixed: flat = c*343 + n
__device__ float g_xres[(size_t)NTOK*CDIM];
__device__ __nv_bfloat16 g_l2h[(size_t)NTOK*CDIM], g_l2l[(size_t)NTOK*CDIM];
__device__ __nv_bfloat16 g_hh[(size_t)NTOK*HIDD], g_hl[(size_t)NTOK*HIDD];
__device__ __nv_bfloat16 g_wqh[288*96], g_wql[288*96];
__device__ __nv_bfloat16 g_f1h[HIDD*96], g_f1l[HIDD*96];
__device__ __nv_bfloat16 g_f2h[96*HIDD], g_f2l[96*HIDD];
__device__ float g_bqkv[288];

// -------------------- weight prep --------------------------------------------
__global__ void k_prep1(const float* __restrict__ wq, const float* __restrict__ bq,
                        const float* __restrict__ wk, const float* __restrict__ bk,
                        const float* __restrict__ wv, const float* __restrict__ bv) {
    int i = blockIdx.x * 256 + threadIdx.x;
    if (i < 3*96*96) {
        int t = i / 9216, r = i % 9216;
        float v = (t == 0) ? wq[r] : (t == 1) ? wk[r] : wv[r];
        bsplit(v, g_wqh[i], g_wql[i]);
    }
    if (i < 288) {
        int t = i / 96, r = i % 96;
        g_bqkv[i] = (t == 0) ? bq[r] : (t == 1) ? bk[r] : bv[r];
    }
}
__global__ void k_prep2(const float* __restrict__ f1w, const float* __restrict__ f2w) {
    int i = blockIdx.x * 256 + threadIdx.x;
    if (i < HIDD*96) {
        bsplit(f1w[i], g_f1h[i], g_f1l[i]);
        bsplit(f2w[i], g_f2h[i], g_f2l[i]);
    }
}

// -------------------- LN1 + roll(-3) + window partition -----------------------
__global__ __launch_bounds__(256)
void k_ln1(const float* __restrict__ x,
           const float* __restrict__ gg, const float* __restrict__ bb) {
    __shared__ float xs[64*101];
    int p0 = blockIdx.x * 64;
    int tid = threadIdx.x, lane = tid & 31, wp = tid >> 5;
    for (int e = tid; e < 96*64; e += 256) {
        int c = e >> 6, i = e & 63;
        xs[i*101 + c] = x[(size_t)c*NTOK + p0 + i];
    }
    __syncthreads();
    #pragma unroll
    for (int ii = wp; ii < 64; ii += 8) {
        int p = p0 + ii;
        int s = p / 3136, r = p % 3136, h = r / 56, w = r % 56;
        int s2 = (s >= 3) ? s - 3 : s + 53;
        int h2 = (h >= 3) ? h - 3 : h + 53;
        int w2 = (w >= 3) ? w - 3 : w + 53;
        int win = (s2/7)*64 + (h2/7)*8 + (w2/7);
        int t   = (s2%7)*49 + (h2%7)*7 + (w2%7);
        float v0 = xs[ii*101 + lane];
        float v1 = xs[ii*101 + lane + 32];
        float v2 = xs[ii*101 + lane + 64];
        float sum = v0 + v1 + v2, sq = v0*v0 + v1*v1 + v2*v2;
        #pragma unroll
        for (int o = 16; o; o >>= 1) {
            sum += __shfl_xor_sync(0xffffffffu, sum, o);
            sq  += __shfl_xor_sync(0xffffffffu, sq, o);
        }
        float mean = sum * (1.f/96.f);
        float var  = sq * (1.f/96.f) - mean*mean;
        float inv  = rsqrtf(var + 1e-5f);
        size_t ob = ((size_t)win*WN + t)*CDIM;
        float y0 = (v0 - mean)*inv*gg[lane]      + bb[lane];
        float y1 = (v1 - mean)*inv*gg[lane + 32] + bb[lane + 32];
        float y2 = (v2 - mean)*inv*gg[lane + 64] + bb[lane + 64];
        bsplit(y0, g_xwh[ob + lane],      g_xwl[ob + lane]);
        bsplit(y1, g_xwh[ob + lane + 32], g_xwl[ob + lane + 32]);
        bsplit(y2, g_xwh[ob + lane + 64], g_xwl[ob + lane + 64]);
    }
}

// -------------------- tensor-core GEMM (bf16 split, mma.sync) ----------------
// D[128,96] = A[128,K] @ W[96(+bn),K]^T ; A = Ah+Al, W = Wh+Wl (3 passes).
// EPI: 0 qkv split fp32, 1 GELU -> bf16 hi/lo planes, 2 res + transposed store
#define SA_STRIDE 104
#define TG_A_HI 0
#define TG_A_LO (128*104)          // bf16 units
#define TG_B_HI (2*128*104)
#define TG_B_LO (2*128*104 + 96*104)
#define TG_SMEM ((2*128*104 + 2*96*104) * 2)   // 93184 bytes

template<int EPI>
__global__ __launch_bounds__(256)
void k_tgemm(const __nv_bfloat16* __restrict__ Ah, const __nv_bfloat16* __restrict__ Al,
             const __nv_bfloat16* __restrict__ Wh, const __nv_bfloat16* __restrict__ Wl,
             const float* __restrict__ bias, int K,
             float* __restrict__ O0, float* __restrict__ O1, float* __restrict__ O2,
             __nv_bfloat16* __restrict__ Oh, __nv_bfloat16* __restrict__ Ol,
             const float* __restrict__ Res, float* __restrict__ OutT) {
    extern __shared__ char smemc[];
    __nv_bfloat16* sA = (__nv_bfloat16*)smemc;
    int tid = threadIdx.x, lane = tid & 31, wid = tid >> 5;
    int g = lane >> 2, tg = lane & 3;
    int bm = blockIdx.x * 128, bn = blockIdx.y * 96;
    int warpM = (wid & 3) * 32, warpN = (wid >> 2) * 48;

    float acc[2][6][4];
    #pragma unroll
    for (int mt = 0; mt < 2; mt++)
        #pragma unroll
        for (int nt = 0; nt < 6; nt++)
            #pragma unroll
            for (int i = 0; i < 4; i++) acc[mt][nt][i] = 0.f;

    int nch = K / 96;
    for (int kc = 0; kc < nch; kc++) {
        // ---- global -> smem (padded stride 104) ----
        const __nv_bfloat16* pAh = Ah + (size_t)bm*K + kc*96;
        const __nv_bfloat16* pAl = Al + (size_t)bm*K + kc*96;
        for (int e = tid; e < 128*24; e += 256) {
            int r = e / 24, c4 = e % 24;
            *(uint2*)(sA + TG_A_HI + r*SA_STRIDE + c4*4) = *(const uint2*)(pAh + (size_t)r*K + c4*4);
            *(uint2*)(sA + TG_A_LO + r*SA_STRIDE + c4*4) = *(const uint2*)(pAl + (size_t)r*K + c4*4);
        }
        const __nv_bfloat16* pWh = Wh + (size_t)bn*K + kc*96;
        const __nv_bfloat16* pWl = Wl + (size_t)bn*K + kc*96;
        for (int e = tid; e < 96*24; e += 256) {
            int r = e / 24, c4 = e % 24;
            *(uint2*)(sA + TG_B_HI + r*SA_STRIDE + c4*4) = *(const uint2*)(pWh + (size_t)r*K + c4*4);
            *(uint2*)(sA + TG_B_LO + r*SA_STRIDE + c4*4) = *(const uint2*)(pWl + (size_t)r*K + c4*4);
        }
        __syncthreads();

        // ---- 3 passes: Ah*Bh, Ah*Bl, Al*Bh ----
        #pragma unroll
        for (int pass = 0; pass < 3; pass++) {
            const __nv_bfloat16* pA = sA + ((pass == 2) ? TG_A_LO : TG_A_HI);
            const __nv_bfloat16* pB = sA + ((pass == 1) ? TG_B_LO : TG_B_HI);
            #pragma unroll
            for (int ks = 0; ks < 6; ks++) {
                int k0 = ks * 16;
                u32 a[2][4];
                #pragma unroll
                for (int mt = 0; mt < 2; mt++) {
                    const __nv_bfloat16* ar = pA + (warpM + mt*16 + g)*SA_STRIDE + k0 + 2*tg;
                    a[mt][0] = *(const u32*)(ar);
                    a[mt][1] = *(const u32*)(ar + 8*SA_STRIDE);
                    a[mt][2] = *(const u32*)(ar + 8);
                    a[mt][3] = *(const u32*)(ar + 8*SA_STRIDE + 8);
                }
                #pragma unroll
                for (int nt = 0; nt < 6; nt++) {
                    const __nv_bfloat16* br = pB + (warpN + nt*8 + g)*SA_STRIDE + k0 + 2*tg;
                    u32 b0 = *(const u32*)(br);
                    u32 b1 = *(const u32*)(br + 8);
                    mma16816(acc[0][nt], a[0][0], a[0][1], a[0][2], a[0][3], b0, b1);
                    mma16816(acc[1][nt], a[1][0], a[1][1], a[1][2], a[1][3], b0, b1);
                }
            }
        }
        __syncthreads();
    }

    // ---- epilogue (D fragment: rows g/g+8, cols 2tg/2tg+1 per tile) ----
    if (EPI == 0) {
        float* O = (blockIdx.y == 0) ? O0 : (blockIdx.y == 1) ? O1 : O2;
        #pragma unroll
        for (int mt = 0; mt < 2; mt++) {
            int r0 = bm + warpM + mt*16 + g;
            #pragma unroll
            for (int nt = 0; nt < 6; nt++) {
                int c = warpN + nt*8 + 2*tg;
                float b0 = bias[bn + c], b1 = bias[bn + c + 1];
                *(float2*)(O + (size_t)r0*96 + c)       = make_float2(acc[mt][nt][0] + b0, acc[mt][nt][1] + b1);
                *(float2*)(O + (size_t)(r0 + 8)*96 + c) = make_float2(acc[mt][nt][2] + b0, acc[mt][nt][3] + b1);
            }
        }
    } else if (EPI == 1) {
        #pragma unroll
        for (int mt = 0; mt < 2; mt++) {
            int r0 = bm + warpM + mt*16 + g;
            #pragma unroll
            for (int nt = 0; nt < 6; nt++) {
                int c = warpN + nt*8 + 2*tg;
                float b0 = bias[bn + c], b1 = bias[bn + c + 1];
                #pragma unroll
                for (int hrow = 0; hrow < 2; hrow++) {
                    int row = r0 + hrow*8;
                    float v0 = gelu_f(acc[mt][nt][2*hrow]   + b0);
                    float v1 = gelu_f(acc[mt][nt][2*hrow+1] + b1);
                    __nv_bfloat16 h0, l0, h1, l1;
                    bsplit(v0, h0, l0);
                    bsplit(v1, h1, l1);
                    *(u32*)(Oh + (size_t)row*HIDD + bn + c) = pack_bf(h0, h1);
                    *(u32*)(Ol + (size_t)row*HIDD + bn + c) = pack_bf(l0, l1);
                }
            }
        }
    } else {
        float* st = (float*)smemc;    // 96 cols x 132 rows
        #pragma unroll
        for (int mt = 0; mt < 2; mt++) {
            int rl = warpM + mt*16 + g;
            #pragma unroll
            for (int nt = 0; nt < 6; nt++) {
                int c = warpN + nt*8 + 2*tg;
                float b0 = bias[c], b1 = bias[c + 1];
                #pragma unroll
                for (int hrow = 0; hrow < 2; hrow++) {
                    int row = rl + hrow*8;
                    const float* rr = Res + (size_t)(bm + row)*96;
                    st[(c)  *132 + row] = acc[mt][nt][2*hrow]   + b0 + rr[c];
                    st[(c+1)*132 + row] = acc[mt][nt][2*hrow+1] + b1 + rr[c+1];
                }
            }
        }
        __syncthreads();
        for (int e = tid; e < 96*128; e += 256) {
            int col = e >> 7, r = e & 127;
            OutT[(size_t)col*NTOK + bm + r] = st[col*132 + r];
        }
    }
}

// -------------------- depthwise 3x3x3 (packed) --------------------------------
__global__ __launch_bounds__(392, 2)
void k_dw(const float* __restrict__ In, const float* __restrict__ Wt,
          const float* __restrict__ Bi, float* __restrict__ Ot) {
    __shared__ float sin_[WN*32];
    __shared__ float wsm[27*32];
    int win = blockIdx.x;
    int c0 = blockIdx.y * 32;
    int tid = threadIdx.x;
    const float* inw = In + (size_t)win*WN*CDIM + c0;
    for (int e = tid; e < WN*8; e += 392) {
        int t = e >> 3, c4 = e & 7;
        *(float4*)(sin_ + t*32 + c4*4) = *(const float4*)(inw + t*96 + c4*4);
    }
    for (int e = tid; e < 27*32; e += 392) {
        int k = e >> 5, cc = e & 31;
        wsm[k*32 + cc] = Wt[(c0 + cc)*27 + k];
    }
    __syncthreads();

    int g = tid & 7, dy = (tid >> 3) % 7, dz = tid / 56;
    int cc = g * 4;
    F4U bias4; bias4.f = *(const float4*)(Bi + c0 + cc);
    u64 ax[7], ay[7];
    #pragma unroll
    for (int x = 0; x < 7; x++) { ax[x] = bias4.u.x; ay[x] = bias4.u.y; }

    #pragma unroll
    for (int kd = 0; kd < 3; kd++) {
        int nz = dz + kd - 1;
        if ((unsigned)nz >= 7u) continue;
        #pragma unroll
        for (int kh = 0; kh < 3; kh++) {
            int ny = dy + kh - 1;
            if ((unsigned)ny >= 7u) continue;
            const float* row = sin_ + (nz*49 + ny*7)*32 + cc;
            F4U iv[7];
            #pragma unroll
            for (int x = 0; x < 7; x++) iv[x].f = *(const float4*)(row + x*32);
            const float* wp_ = wsm + (kd*9 + kh*3)*32 + cc;
            F4U w0, w1, w2;
            w0.f = *(const float4*)(wp_);
            w1.f = *(const float4*)(wp_ + 32);
            w2.f = *(const float4*)(wp_ + 64);
            #pragma unroll
            for (int x = 1; x < 7; x++) {
                ax[x] = ffma2(w0.u.x, iv[x-1].u.x, ax[x]);
                ay[x] = ffma2(w0.u.y, iv[x-1].u.y, ay[x]);
            }
            #pragma unroll
            for (int x = 0; x < 7; x++) {
                ax[x] = ffma2(w1.u.x, iv[x].u.x, ax[x]);
                ay[x] = ffma2(w1.u.y, iv[x].u.y, ay[x]);
            }
            #pragma unroll
            for (int x = 0; x < 6; x++) {
                ax[x] = ffma2(w2.u.x, iv[x+1].u.x, ax[x]);
                ay[x] = ffma2(w2.u.y, iv[x+1].u.y, ay[x]);
            }
        }
    }

    float* outw = Ot + (size_t)win*WN*CDIM + (dz*49 + dy*7)*96 + c0 + cc;
    #pragma unroll
    for (int x = 0; x < 7; x++) {
        F4U o; o.u.x = ax[x]; o.u.y = ay[x];
        *(float4*)(outw + x*96) = o.f;
    }
}

// -------------------- fused attention helper ---------------------------------
template<int JB, int JN>
__device__ __forceinline__ void qk_dot(const float* __restrict__ ks,
                                       const float* __restrict__ myq,
                                       int lane, float sc[4][11]) {
    u64 acc2[4][JN];
    #pragma unroll
    for (int qi = 0; qi < 4; qi++)
        #pragma unroll
        for (int jj = 0; jj < JN; jj++) acc2[qi][jj] = 0ull;

    #pragma unroll 4
    for (int c4 = 0; c4 < 24; c4++) {
        F4U qv0, qv1, qv2, qv3;
        qv0.f = *(const float4*)(myq + 0*344 + c4*4);
        qv1.f = *(const float4*)(myq + 1*344 + c4*4);
        qv2.f = *(const float4*)(myq + 2*344 + c4*4);
        qv3.f = *(const float4*)(myq + 3*344 + c4*4);
        #pragma unroll
        for (int jj = 0; jj < JN; jj++) {
            F4U kv;
            kv.f = *(const float4*)(ks + (lane + 32*(JB + jj))*100 + c4*4);
            acc2[0][jj] = ffma2(kv.u.x, qv0.u.x, acc2[0][jj]);
            acc2[0][jj] = ffma2(kv.u.y, qv0.u.y, acc2[0][jj]);
            acc2[1][jj] = ffma2(kv.u.x, qv1.u.x, acc2[1][jj]);
            acc2[1][jj] = ffma2(kv.u.y, qv1.u.y, acc2[1][jj]);
            acc2[2][jj] = ffma2(kv.u.x, qv2.u.x, acc2[2][jj]);
            acc2[2][jj] = ffma2(kv.u.y, qv2.u.y, acc2[2][jj]);
            acc2[3][jj] = ffma2(kv.u.x, qv3.u.x, acc2[3][jj]);
            acc2[3][jj] = ffma2(kv.u.y, qv3.u.y, acc2[3][jj]);
        }
    }
    #pragma unroll
    for (int qi = 0; qi < 4; qi++)
        #pragma unroll
        for (int jj = 0; jj < JN; jj++)
            sc[qi][JB + jj] = hadd2(acc2[qi][jj]);
}

// -------------------- fused attention -----------------------------------------
__global__ __launch_bounds__(512)
void k_attn(const float* __restrict__ Q, const float* __restrict__ Km,
            const float* __restrict__ Vm) {
    extern __shared__ float sm[];
    float* kv   = sm;            // 352*100
    float* pbuf = sm + 352*100;  // 64*344
    int win = blockIdx.x;
    int tid = threadIdx.x, lane = tid & 31, wp = tid >> 5;
    const float* kw = Km + (size_t)win*WN*CDIM;
    const float* vw = Vm + (size_t)win*WN*CDIM;
    const float* qw = Q  + (size_t)win*WN*CDIM;
    float* ob = g_ot + (size_t)win*WN*CDIM;

    int ws = win >> 6, hs = (win >> 3) & 7, wd = win & 7;
    bool bz = (ws == 7), bh = (hs == 7), bw = (wd == 7);
    const float scale = 0.10206207261596575f;

    unsigned mzm = 0, mhm = 0, mwm = 0, mvm = 0;
    #pragma unroll
    for (int j = 0; j < 11; j++) {
        int m = lane + 32*j;
        if (m < WN) {
            int dzm = m / 49, rm = m % 49, dym = rm / 7, dxm = rm % 7;
            if (dzm < 4) mzm |= 1u << j;
            if (dym < 4) mhm |= 1u << j;
            if (dxm < 4) mwm |= 1u << j;
            mvm |= 1u << j;
        }
    }

    float* myrows = pbuf + wp*4*344;

    for (int chunk = 0; chunk < 6; chunk++) {
        int qbase = chunk*64 + wp*4;
        __syncthreads();
        for (int e = tid; e < WN*CDIM; e += 512)
            kv[(e/96)*100 + (e%96)] = kw[e];
        __syncthreads();

        #pragma unroll
        for (int qi = 0; qi < 4; qi++) {
            int q = qbase + qi;
            if (q < WN) {
                myrows[qi*344 + lane]      = qw[q*96 + lane]      * scale;
                myrows[qi*344 + lane + 32] = qw[q*96 + lane + 32] * scale;
                myrows[qi*344 + lane + 64] = qw[q*96 + lane + 64] * scale;
            }
        }
        __syncwarp();
        float sc[4][11];
        qk_dot<0, 6>(kv, myrows, lane, sc);
        qk_dot<6, 5>(kv, myrows, lane, sc);
        __syncwarp();
        #pragma unroll
        for (int qi = 0; qi < 4; qi++) {
            int q = qbase + qi;
            if (q >= WN) break;
            int dzq = q / 49, rq = q % 49, dyq = rq / 7, dxq = rq % 7;
            bool gz = dzq < 4, gh = dyq < 4, gw = dxq < 4;
            float mx = -1e30f;
            #pragma unroll
            for (int j = 0; j < 11; j++) {
                float v;
                if (mvm & (1u << j)) {
                    bool same = (!bz || (gz == ((mzm >> j) & 1))) &&
                                (!bh || (gh == ((mhm >> j) & 1))) &&
                                (!bw || (gw == ((mwm >> j) & 1)));
                    v = sc[qi][j] + (same ? 0.f : -100.f);
                } else v = -1e30f;
                sc[qi][j] = v;
                mx = fmaxf(mx, v);
            }
            #pragma unroll
            for (int o = 16; o; o >>= 1) mx = fmaxf(mx, __shfl_xor_sync(0xffffffffu, mx, o));
            float ssum = 0.f;
            #pragma unroll
            for (int j = 0; j < 11; j++) { sc[qi][j] = __expf(sc[qi][j] - mx); ssum += sc[qi][j]; }
            #pragma unroll
            for (int o = 16; o; o >>= 1) ssum += __shfl_xor_sync(0xffffffffu, ssum, o);
            float rinv = 1.f / ssum;
            #pragma unroll
            for (int j = 0; j < 11; j++) {
                int m = lane + 32*j;
                if (m < WN) myrows[qi*344 + m] = sc[qi][j] * rinv;
            }
        }
        if (lane < 4) myrows[lane*344 + 343] = 0.f;
        __syncthreads();

        for (int e = tid; e < WN*CDIM; e += 512)
            kv[(e/96)*100 + (e%96)] = vw[e];
        for (int e = tid; e < 9*100; e += 512)
            kv[343*100 + e] = 0.f;
        __syncthreads();

        u64 acc2[4][3] = {};
        #pragma unroll 2
        for (int mi = 0; mi < 344; mi += 2) {
            u64 v0 = pack2(kv[mi*100 + lane],      kv[mi*100 + 100 + lane]);
            u64 v1 = pack2(kv[mi*100 + lane + 32], kv[mi*100 + 132 + lane]);
            u64 v2 = pack2(kv[mi*100 + lane + 64], kv[mi*100 + 164 + lane]);
            #pragma unroll
            for (int qi = 0; qi < 4; qi++) {
                u64 pp = *(const u64*)(myrows + qi*344 + mi);
                acc2[qi][0] = ffma2(pp, v0, acc2[qi][0]);
                acc2[qi][1] = ffma2(pp, v1, acc2[qi][1]);
                acc2[qi][2] = ffma2(pp, v2, acc2[qi][2]);
            }
        }
        #pragma unroll
        for (int qi = 0; qi < 4; qi++) {
            myrows[ lane      *4 + qi] = hadd2(acc2[qi][0]);
            myrows[(lane + 32)*4 + qi] = hadd2(acc2[qi][1]);
            myrows[(lane + 64)*4 + qi] = hadd2(acc2[qi][2]);
        }
        __syncwarp();
        #pragma unroll
        for (int e = lane; e < 384; e += 32) {
            int c = e >> 2, qi = e & 3;
            int q = qbase + qi;
            if (q < WN) ob[(size_t)c*WN + q] = myrows[e];
        }
    }
}

// -------------------- window-reverse + roll(+3) + residual + LN2 --------------
__global__ __launch_bounds__(256)
void k_resln2(const float* __restrict__ x,
              const float* __restrict__ gg, const float* __restrict__ bb) {
    __shared__ float xs[32*101];
    int p0 = blockIdx.x * 32;
    int tid = threadIdx.x, lane = tid & 31, wp = tid >> 5;
    for (int e = tid; e < 96*32; e += 256) {
        int c = e >> 5, i = e & 31;
        xs[i*101 + c] = x[(size_t)c*NTOK + p0 + i];
    }
    __syncthreads();
    #pragma unroll
    for (int ii = wp; ii < 32; ii += 8) {
        int p = p0 + ii;
        int s = p / 3136, r = p % 3136, h = r / 56, w = r % 56;
        int s2 = (s >= 3) ? s - 3 : s + 53;
        int h2 = (h >= 3) ? h - 3 : h + 53;
        int w2 = (w >= 3) ? w - 3 : w + 53;
        int win = (s2/7)*64 + (h2/7)*8 + (w2/7);
        int np  = (s2%7)*49 + (h2%7)*7 + (w2%7);
        const float* ov = g_ot + (size_t)win*WN*CDIM + np*96;
        float v0 = xs[ii*101 + lane]      + ov[lane];
        float v1 = xs[ii*101 + lane + 32] + ov[lane + 32];
        float v2 = xs[ii*101 + lane + 64] + ov[lane + 64];
        float* xr = g_xres + (size_t)p*CDIM;
        xr[lane] = v0; xr[lane + 32] = v1; xr[lane + 64] = v2;
        float sum = v0 + v1 + v2, sq = v0*v0 + v1*v1 + v2*v2;
        #pragma unroll
        for (int o = 16; o; o >>= 1) {
            sum += __shfl_xor_sync(0xffffffffu, sum, o);
            sq  += __shfl_xor_sync(0xffffffffu, sq, o);
        }
        float mean = sum * (1.f/96.f);
        float var  = sq * (1.f/96.f) - mean*mean;
        float inv  = rsqrtf(var + 1e-5f);
        size_t yo = (size_t)p*CDIM;
        float y0 = (v0 - mean)*inv*gg[lane]      + bb[lane];
        float y1 = (v1 - mean)*inv*gg[lane + 32] + bb[lane + 32];
        float y2 = (v2 - mean)*inv*gg[lane + 64] + bb[lane + 64];
        bsplit(y0, g_l2h[yo + lane],      g_l2l[yo + lane]);
        bsplit(y1, g_l2h[yo + lane + 32], g_l2l[yo + lane + 32]);
        bsplit(y2, g_l2h[yo + lane + 64], g_l2l[yo + lane + 64]);
    }
}

// -------------------- launch ---------------------------------------------------
extern "C" void kernel_launch(void* const* d_in, const int* in_sizes, int n_in,
                              void* d_out, int out_size) {
    const float* x   = (const float*)d_in[0];
    const float* n1g = (const float*)d_in[1];
    const float* n1b = (const float*)d_in[2];
    const float* wq  = (const float*)d_in[3];
    const float* bq  = (const float*)d_in[4];
    const float* wk  = (const float*)d_in[5];
    const float* bk  = (const float*)d_in[6];
    const float* wv  = (const float*)d_in[7];
    const float* bv  = (const float*)d_in[8];
    const float* dqw = (const float*)d_in[9];
    const float* dqb = (const float*)d_in[10];
    const float* dkw = (const float*)d_in[11];
    const float* dkb = (const float*)d_in[12];
    const float* dvw = (const float*)d_in[13];
    const float* dvb = (const float*)d_in[14];
    const float* n2g = (const float*)d_in[15];
    const float* n2b = (const float*)d_in[16];
    const float* f1w = (const float*)d_in[17];
    const float* f1b = (const float*)d_in[18];
    const float* f2w = (const float*)d_in[19];
    const float* f2b = (const float*)d_in[20];
    float* out = (float*)d_out;

    float *pqp, *pkp, *pvp, *pq, *pk, *pv, *pxres, *pbqkv;
    __nv_bfloat16 *pxwh, *pxwl, *pl2h, *pl2l, *phh, *phl, *pwqh, *pwql, *pf1h, *pf1l, *pf2h, *pf2l;
    cudaGetSymbolAddress((void**)&pqp,  g_qp);
    cudaGetSymbolAddress((void**)&pkp,  g_kp);
    cudaGetSymbolAddress((void**)&pvp,  g_vp);
    cudaGetSymbolAddress((void**)&pq,   g_q);
    cudaGetSymbolAddress((void**)&pk,   g_k);
    cudaGetSymbolAddress((void**)&pv,   g_v);
    cudaGetSymbolAddress((void**)&pxres,g_xres);
    cudaGetSymbolAddress((void**)&pbqkv,g_bqkv);
    cudaGetSymbolAddress((void**)&pxwh, g_xwh);
    cudaGetSymbolAddress((void**)&pxwl, g_xwl);
    cudaGetSymbolAddress((void**)&pl2h, g_l2h);
    cudaGetSymbolAddress((void**)&pl2l, g_l2l);
    cudaGetSymbolAddress((void**)&phh,  g_hh);
    cudaGetSymbolAddress((void**)&phl,  g_hl);
    cudaGetSymbolAddress((void**)&pwqh, g_wqh);
    cudaGetSymbolAddress((void**)&pwql, g_wql);
    cudaGetSymbolAddress((void**)&pf1h, g_f1h);
    cudaGetSymbolAddress((void**)&pf1l, g_f1l);
    cudaGetSymbolAddress((void**)&pf2h, g_f2h);
    cudaGetSymbolAddress((void**)&pf2l, g_f2l);

    const int ATTN_SMEM = (352*100 + 64*344) * 4;
    cudaFuncSetAttribute(k_attn, cudaFuncAttributeMaxDynamicSharedMemorySize, ATTN_SMEM);
    cudaFuncSetAttribute(k_tgemm<0>, cudaFuncAttributeMaxDynamicSharedMemorySize, TG_SMEM);
    cudaFuncSetAttribute(k_tgemm<1>, cudaFuncAttributeMaxDynamicSharedMemorySize, TG_SMEM);
    cudaFuncSetAttribute(k_tgemm<2>, cudaFuncAttributeMaxDynamicSharedMemorySize, TG_SMEM);

    k_prep1<<<(3*96*96 + 255)/256, 256>>>(wq, bq, wk, bk, wv, bv);
    k_prep2<<<(HIDD*96 + 255)/256, 256>>>(f1w, f2w);
    k_ln1<<<NTOK/64, 256>>>(x, n1g, n1b);

    // qkv: D = xw @ wqkv^T (+bias), split to 3 buffers
    dim3 gq(NTOK/128, 3);
    k_tgemm<0><<<gq, 256, TG_SMEM>>>(pxwh, pxwl, pwqh, pwql, pbqkv, 96,
                                     pqp, pkp, pvp, nullptr, nullptr, nullptr, nullptr);

    dim3 gdw(NW, 3);
    k_dw<<<gdw, 392>>>(pqp, dqw, dqb, pq);
    k_dw<<<gdw, 392>>>(pkp, dkw, dkb, pk);
    k_dw<<<gdw, 392>>>(pvp, dvw, dvb, pv);

    k_attn<<<NW, 512, ATTN_SMEM>>>(pq, pk, pv);

    k_resln2<<<NTOK/32, 256>>>(x, n2g, n2b);

    // MLP1: GELU(ln2 @ f1w^T + f1b) -> bf16 hi/lo planes
    dim3 g2(NTOK/128, HIDD/96);
    k_tgemm<1><<<g2, 256, TG_SMEM>>>(pl2h, pl2l, pf1h, pf1l, f1b, 96,
                                     nullptr, nullptr, nullptr, phh, phl, nullptr, nullptr);
    // MLP2: out^T = (h @ f2w^T + f2b + xres)
    dim3 g3(NTOK/128, 1);
    k_tgemm<2><<<g3, 256, TG_SMEM>>>(phh, phl, pf2h, pf2l, f2b, HIDD,
                                     nullptr, nullptr, nullptr, nullptr, nullptr, pxres, out);
}

// round 8
// speedup vs baseline: 1.1764x; 1.1288x over previous
#include <cuda_runtime.h>
#include <cuda_bf16.h>
#include <math.h>
#include <stdint.h>

#define NTOK 175616   // 56*56*56
#define CDIM 96
#define NW   512
#define WN   343
#define HIDD 384

typedef unsigned long long u64;
typedef unsigned int u32;
union F4U { float4 f; ulonglong2 u; };

__device__ __forceinline__ u64 ffma2(u64 a, u64 b, u64 c) {
    u64 d; asm("fma.rn.f32x2 %0, %1, %2, %3;" : "=l"(d) : "l"(a), "l"(b), "l"(c));
    return d;
}
__device__ __forceinline__ u64 pack2(float lo, float hi) {
    u64 r; asm("mov.b64 %0, {%1, %2};" : "=l"(r) : "f"(lo), "f"(hi));
    return r;
}
__device__ __forceinline__ float2 unpack2(u64 v) {
    float2 r; asm("mov.b64 {%0, %1}, %2;" : "=f"(r.x), "=f"(r.y) : "l"(v));
    return r;
}
__device__ __forceinline__ float hadd2(u64 v) { float2 t = unpack2(v); return t.x + t.y; }

__device__ __forceinline__ void bsplit(float v, __nv_bfloat16& h, __nv_bfloat16& l) {
    h = __float2bfloat16_rn(v);
    l = __float2bfloat16_rn(v - __bfloat162float(h));
}
__device__ __forceinline__ u32 pack_bf(__nv_bfloat16 a, __nv_bfloat16 b) {
    return (u32)__bfloat16_as_ushort(a) | ((u32)__bfloat16_as_ushort(b) << 16);
}
__device__ __forceinline__ float gelu_f(float v) {
    return 0.5f * v * (1.f + erff(v * 0.70710678118654752f));
}
__device__ __forceinline__ void mma16816(float* d, const u32* a, u32 b0, u32 b1) {
    asm volatile("mma.sync.aligned.m16n8k16.row.col.f32.bf16.bf16.f32 "
                 "{%0,%1,%2,%3}, {%4,%5,%6,%7}, {%8,%9}, {%0,%1,%2,%3};"
                 : "+f"(d[0]), "+f"(d[1]), "+f"(d[2]), "+f"(d[3])
                 : "r"(a[0]), "r"(a[1]), "r"(a[2]), "r"(a[3]), "r"(b0), "r"(b1));
}
__device__ __forceinline__ void ldmx4(u32* r, const __nv_bfloat16* p) {
    u32 addr = (u32)__cvta_generic_to_shared(p);
    asm volatile("ldmatrix.sync.aligned.m8n8.x4.shared.b16 {%0,%1,%2,%3}, [%4];"
                 : "=r"(r[0]), "=r"(r[1]), "=r"(r[2]), "=r"(r[3]) : "r"(addr));
}

// -------------------- scratch (device globals) -------------------------------
__device__ __nv_bfloat16 g_xwh[(size_t)NTOK*CDIM], g_xwl[(size_t)NTOK*CDIM];
__device__ float g_qp [(size_t)NTOK*CDIM];
__device__ float g_kp [(size_t)NTOK*CDIM];
__device__ float g_vp [(size_t)NTOK*CDIM];
__device__ float g_q  [(size_t)NTOK*CDIM];
__device__ float g_k  [(size_t)NTOK*CDIM];
__device__ float g_v  [(size_t)NTOK*CDIM];
__device__ float g_ot [(size_t)NTOK*CDIM];   // attention out, axis-mixed: flat = c*343 + n
__device__ float g_xres[(size_t)NTOK*CDIM];
__device__ __nv_bfloat16 g_l2h[(size_t)NTOK*CDIM], g_l2l[(size_t)NTOK*CDIM];
__device__ __nv_bfloat16 g_hh[(size_t)NTOK*HIDD], g_hl[(size_t)NTOK*HIDD];
__device__ __nv_bfloat16 g_wqh[288*96], g_wql[288*96];
__device__ __nv_bfloat16 g_f1h[HIDD*96], g_f1l[HIDD*96];
__device__ __nv_bfloat16 g_f2h[96*HIDD], g_f2l[96*HIDD];
__device__ float g_bqkv[288];

// -------------------- weight prep --------------------------------------------
__global__ void k_prep1(const float* __restrict__ wq, const float* __restrict__ bq,
                        const float* __restrict__ wk, const float* __restrict__ bk,
                        const float* __restrict__ wv, const float* __restrict__ bv) {
    int i = blockIdx.x * 256 + threadIdx.x;
    if (i < 3*96*96) {
        int t = i / 9216, r = i % 9216;
        float v = (t == 0) ? wq[r] : (t == 1) ? wk[r] : wv[r];
        bsplit(v, g_wqh[i], g_wql[i]);
    }
    if (i < 288) {
        int t = i / 96, r = i % 96;
        g_bqkv[i] = (t == 0) ? bq[r] : (t == 1) ? bk[r] : bv[r];
    }
}
__global__ void k_prep2(const float* __restrict__ f1w, const float* __restrict__ f2w) {
    int i = blockIdx.x * 256 + threadIdx.x;
    if (i < HIDD*96) {
        bsplit(f1w[i], g_f1h[i], g_f1l[i]);
        bsplit(f2w[i], g_f2h[i], g_f2l[i]);
    }
}

// -------------------- LN1 + roll(-3) + window partition -----------------------
__global__ __launch_bounds__(256)
void k_ln1(const float* __restrict__ x,
           const float* __restrict__ gg, const float* __restrict__ bb) {
    __shared__ float xs[64*101];
    int p0 = blockIdx.x * 64;
    int tid = threadIdx.x, lane = tid & 31, wp = tid >> 5;
    for (int e = tid; e < 96*64; e += 256) {
        int c = e >> 6, i = e & 63;
        xs[i*101 + c] = x[(size_t)c*NTOK + p0 + i];
    }
    __syncthreads();
    #pragma unroll
    for (int ii = wp; ii < 64; ii += 8) {
        int p = p0 + ii;
        int s = p / 3136, r = p % 3136, h = r / 56, w = r % 56;
        int s2 = (s >= 3) ? s - 3 : s + 53;
        int h2 = (h >= 3) ? h - 3 : h + 53;
        int w2 = (w >= 3) ? w - 3 : w + 53;
        int win = (s2/7)*64 + (h2/7)*8 + (w2/7);
        int t   = (s2%7)*49 + (h2%7)*7 + (w2%7);
        float v0 = xs[ii*101 + lane];
        float v1 = xs[ii*101 + lane + 32];
        float v2 = xs[ii*101 + lane + 64];
        float sum = v0 + v1 + v2, sq = v0*v0 + v1*v1 + v2*v2;
        #pragma unroll
        for (int o = 16; o; o >>= 1) {
            sum += __shfl_xor_sync(0xffffffffu, sum, o);
            sq  += __shfl_xor_sync(0xffffffffu, sq, o);
        }
        float mean = sum * (1.f/96.f);
        float var  = sq * (1.f/96.f) - mean*mean;
        float inv  = rsqrtf(var + 1e-5f);
        size_t ob = ((size_t)win*WN + t)*CDIM;
        float y0 = (v0 - mean)*inv*gg[lane]      + bb[lane];
        float y1 = (v1 - mean)*inv*gg[lane + 32] + bb[lane + 32];
        float y2 = (v2 - mean)*inv*gg[lane + 64] + bb[lane + 64];
        bsplit(y0, g_xwh[ob + lane],      g_xwl[ob + lane]);
        bsplit(y1, g_xwh[ob + lane + 32], g_xwl[ob + lane + 32]);
        bsplit(y2, g_xwh[ob + lane + 64], g_xwl[ob + lane + 64]);
    }
}

// -------------------- tensor-core GEMM (bf16 split, mma.sync + ldmatrix) -----
// D[128,96] = A[128,K] @ W[96(+bn),K]^T ; A = Ah+Al, W = Wh+Wl (3 passes).
// EPI: 0 qkv split fp32, 1 GELU -> bf16 hi/lo planes, 2 res + transposed store
#define SA_STRIDE 104
#define TG_A_HI 0
#define TG_A_LO (128*104)          // bf16 units
#define TG_B_HI (2*128*104)
#define TG_B_LO (2*128*104 + 96*104)
#define TG_SMEM ((2*128*104 + 2*96*104) * 2)   // 93184 bytes

template<int EPI>
__global__ __launch_bounds__(256, 2)
void k_tgemm(const __nv_bfloat16* __restrict__ Ah, const __nv_bfloat16* __restrict__ Al,
             const __nv_bfloat16* __restrict__ Wh, const __nv_bfloat16* __restrict__ Wl,
             const float* __restrict__ bias, int K,
             float* __restrict__ O0, float* __restrict__ O1, float* __restrict__ O2,
             __nv_bfloat16* __restrict__ Oh, __nv_bfloat16* __restrict__ Ol,
             const float* __restrict__ Res, float* __restrict__ OutT) {
    extern __shared__ char smemc[];
    __nv_bfloat16* sA = (__nv_bfloat16*)smemc;
    int tid = threadIdx.x, lane = tid & 31, wid = tid >> 5;
    int g = lane >> 2, tg = lane & 3;
    int bm = blockIdx.x * 128, bn = blockIdx.y * 96;
    int warpM = (wid & 3) * 32, warpN = (wid >> 2) * 48;
    // ldmatrix lane-derived address offsets
    int lr = (lane & 7) + ((lane & 8) ? 8 : 0);
    int lc = (lane & 16) ? 8 : 0;

    float acc[2][6][4];
    #pragma unroll
    for (int mt = 0; mt < 2; mt++)
        #pragma unroll
        for (int nt = 0; nt < 6; nt++)
            #pragma unroll
            for (int i = 0; i < 4; i++) acc[mt][nt][i] = 0.f;

    int nch = K / 96;
    for (int kc = 0; kc < nch; kc++) {
        // ---- global -> smem (padded stride 104) ----
        const __nv_bfloat16* pAh = Ah + (size_t)bm*K + kc*96;
        const __nv_bfloat16* pAl = Al + (size_t)bm*K + kc*96;
        for (int e = tid; e < 128*24; e += 256) {
            int r = e / 24, c4 = e % 24;
            *(uint2*)(sA + TG_A_HI + r*SA_STRIDE + c4*4) = *(const uint2*)(pAh + (size_t)r*K + c4*4);
            *(uint2*)(sA + TG_A_LO + r*SA_STRIDE + c4*4) = *(const uint2*)(pAl + (size_t)r*K + c4*4);
        }
        const __nv_bfloat16* pWh = Wh + (size_t)bn*K + kc*96;
        const __nv_bfloat16* pWl = Wl + (size_t)bn*K + kc*96;
        for (int e = tid; e < 96*24; e += 256) {
            int r = e / 24, c4 = e % 24;
            *(uint2*)(sA + TG_B_HI + r*SA_STRIDE + c4*4) = *(const uint2*)(pWh + (size_t)r*K + c4*4);
            *(uint2*)(sA + TG_B_LO + r*SA_STRIDE + c4*4) = *(const uint2*)(pWl + (size_t)r*K + c4*4);
        }
        __syncthreads();

        // ---- mainloop: per k-step load all fragments once, 36 MMAs ----
        #pragma unroll
        for (int ks = 0; ks < 6; ks++) {
            int k0 = ks * 16;
            u32 ah[2][4], al_[2][4];
            #pragma unroll
            for (int mt = 0; mt < 2; mt++) {
                int ro = (warpM + mt*16 + lr)*SA_STRIDE + k0 + lc;
                ldmx4(ah[mt],  sA + TG_A_HI + ro);
                ldmx4(al_[mt], sA + TG_A_LO + ro);
            }
            u32 bh[3][4], bl[3][4];
            #pragma unroll
            for (int np = 0; np < 3; np++) {
                int ro = (warpN + np*16 + lr)*SA_STRIDE + k0 + lc;
                ldmx4(bh[np], sA + TG_B_HI + ro);
                ldmx4(bl[np], sA + TG_B_LO + ro);
            }
            #pragma unroll
            for (int np = 0; np < 3; np++) {
                #pragma unroll
                for (int mt = 0; mt < 2; mt++) {
                    mma16816(acc[mt][2*np],   ah[mt],  bh[np][0], bh[np][2]);
                    mma16816(acc[mt][2*np+1], ah[mt],  bh[np][1], bh[np][3]);
                    mma16816(acc[mt][2*np],   ah[mt],  bl[np][0], bl[np][2]);
                    mma16816(acc[mt][2*np+1], ah[mt],  bl[np][1], bl[np][3]);
                    mma16816(acc[mt][2*np],   al_[mt], bh[np][0], bh[np][2]);
                    mma16816(acc[mt][2*np+1], al_[mt], bh[np][1], bh[np][3]);
                }
            }
        }
        __syncthreads();
    }

    // ---- epilogue (D fragment: rows g/g+8, cols 2tg/2tg+1 per tile) ----
    if (EPI == 0) {
        float* O = (blockIdx.y == 0) ? O0 : (blockIdx.y == 1) ? O1 : O2;
        #pragma unroll
        for (int mt = 0; mt < 2; mt++) {
            int r0 = bm + warpM + mt*16 + g;
            #pragma unroll
            for (int nt = 0; nt < 6; nt++) {
                int c = warpN + nt*8 + 2*tg;
                float b0 = bias[bn + c], b1 = bias[bn + c + 1];
                *(float2*)(O + (size_t)r0*96 + c)       = make_float2(acc[mt][nt][0] + b0, acc[mt][nt][1] + b1);
                *(float2*)(O + (size_t)(r0 + 8)*96 + c) = make_float2(acc[mt][nt][2] + b0, acc[mt][nt][3] + b1);
            }
        }
    } else if (EPI == 1) {
        #pragma unroll
        for (int mt = 0; mt < 2; mt++) {
            int r0 = bm + warpM + mt*16 + g;
            #pragma unroll
            for (int nt = 0; nt < 6; nt++) {
                int c = warpN + nt*8 + 2*tg;
                float b0 = bias[bn + c], b1 = bias[bn + c + 1];
                #pragma unroll
                for (int hrow = 0; hrow < 2; hrow++) {
                    int row = r0 + hrow*8;
                    float v0 = gelu_f(acc[mt][nt][2*hrow]   + b0);
                    float v1 = gelu_f(acc[mt][nt][2*hrow+1] + b1);
                    __nv_bfloat16 h0, l0, h1, l1;
                    bsplit(v0, h0, l0);
                    bsplit(v1, h1, l1);
                    *(u32*)(Oh + (size_t)row*HIDD + bn + c) = pack_bf(h0, h1);
                    *(u32*)(Ol + (size_t)row*HIDD + bn + c) = pack_bf(l0, l1);
                }
            }
        }
    } else {
        float* st = (float*)smemc;    // 96 cols x 132 rows
        #pragma unroll
        for (int mt = 0; mt < 2; mt++) {
            int rl = warpM + mt*16 + g;
            #pragma unroll
            for (int nt = 0; nt < 6; nt++) {
                int c = warpN + nt*8 + 2*tg;
                float b0 = bias[c], b1 = bias[c + 1];
                #pragma unroll
                for (int hrow = 0; hrow < 2; hrow++) {
                    int row = rl + hrow*8;
                    const float* rr = Res + (size_t)(bm + row)*96;
                    st[(c)  *132 + row] = acc[mt][nt][2*hrow]   + b0 + rr[c];
                    st[(c+1)*132 + row] = acc[mt][nt][2*hrow+1] + b1 + rr[c+1];
                }
            }
        }
        __syncthreads();
        for (int e = tid; e < 96*128; e += 256) {
            int col = e >> 7, r = e & 127;
            OutT[(size_t)col*NTOK + bm + r] = st[col*132 + r];
        }
    }
}

// -------------------- depthwise 3x3x3 (packed) --------------------------------
__global__ __launch_bounds__(392, 2)
void k_dw(const float* __restrict__ In, const float* __restrict__ Wt,
          const float* __restrict__ Bi, float* __restrict__ Ot) {
    __shared__ float sin_[WN*32];
    __shared__ float wsm[27*32];
    int win = blockIdx.x;
    int c0 = blockIdx.y * 32;
    int tid = threadIdx.x;
    const float* inw = In + (size_t)win*WN*CDIM + c0;
    for (int e = tid; e < WN*8; e += 392) {
        int t = e >> 3, c4 = e & 7;
        *(float4*)(sin_ + t*32 + c4*4) = *(const float4*)(inw + t*96 + c4*4);
    }
    for (int e = tid; e < 27*32; e += 392) {
        int k = e >> 5, cc = e & 31;
        wsm[k*32 + cc] = Wt[(c0 + cc)*27 + k];
    }
    __syncthreads();

    int g = tid & 7, dy = (tid >> 3) % 7, dz = tid / 56;
    int cc = g * 4;
    F4U bias4; bias4.f = *(const float4*)(Bi + c0 + cc);
    u64 ax[7], ay[7];
    #pragma unroll
    for (int x = 0; x < 7; x++) { ax[x] = bias4.u.x; ay[x] = bias4.u.y; }

    #pragma unroll
    for (int kd = 0; kd < 3; kd++) {
        int nz = dz + kd - 1;
        if ((unsigned)nz >= 7u) continue;
        #pragma unroll
        for (int kh = 0; kh < 3; kh++) {
            int ny = dy + kh - 1;
            if ((unsigned)ny >= 7u) continue;
            const float* row = sin_ + (nz*49 + ny*7)*32 + cc;
            F4U iv[7];
            #pragma unroll
            for (int x = 0; x < 7; x++) iv[x].f = *(const float4*)(row + x*32);
            const float* wp_ = wsm + (kd*9 + kh*3)*32 + cc;
            F4U w0, w1, w2;
            w0.f = *(const float4*)(wp_);
            w1.f = *(const float4*)(wp_ + 32);
            w2.f = *(const float4*)(wp_ + 64);
            #pragma unroll
            for (int x = 1; x < 7; x++) {
                ax[x] = ffma2(w0.u.x, iv[x-1].u.x, ax[x]);
                ay[x] = ffma2(w0.u.y, iv[x-1].u.y, ay[x]);
            }
            #pragma unroll
            for (int x = 0; x < 7; x++) {
                ax[x] = ffma2(w1.u.x, iv[x].u.x, ax[x]);
                ay[x] = ffma2(w1.u.y, iv[x].u.y, ay[x]);
            }
            #pragma unroll
            for (int x = 0; x < 6; x++) {
                ax[x] = ffma2(w2.u.x, iv[x+1].u.x, ax[x]);
                ay[x] = ffma2(w2.u.y, iv[x+1].u.y, ay[x]);
            }
        }
    }

    float* outw = Ot + (size_t)win*WN*CDIM + (dz*49 + dy*7)*96 + c0 + cc;
    #pragma unroll
    for (int x = 0; x < 7; x++) {
        F4U o; o.u.x = ax[x]; o.u.y = ay[x];
        *(float4*)(outw + x*96) = o.f;
    }
}

// -------------------- fused attention helper ---------------------------------
template<int JB, int JN>
__device__ __forceinline__ void qk_dot(const float* __restrict__ ks,
                                       const float* __restrict__ myq,
                                       int lane, float sc[4][11]) {
    u64 acc2[4][JN];
    #pragma unroll
    for (int qi = 0; qi < 4; qi++)
        #pragma unroll
        for (int jj = 0; jj < JN; jj++) acc2[qi][jj] = 0ull;

    #pragma unroll 4
    for (int c4 = 0; c4 < 24; c4++) {
        F4U qv0, qv1, qv2, qv3;
        qv0.f = *(const float4*)(myq + 0*344 + c4*4);
        qv1.f = *(const float4*)(myq + 1*344 + c4*4);
        qv2.f = *(const float4*)(myq + 2*344 + c4*4);
        qv3.f = *(const float4*)(myq + 3*344 + c4*4);
        #pragma unroll
        for (int jj = 0; jj < JN; jj++) {
            F4U kv;
            kv.f = *(const float4*)(ks + (lane + 32*(JB + jj))*100 + c4*4);
            acc2[0][jj] = ffma2(kv.u.x, qv0.u.x, acc2[0][jj]);
            acc2[0][jj] = ffma2(kv.u.y, qv0.u.y, acc2[0][jj]);
            acc2[1][jj] = ffma2(kv.u.x, qv1.u.x, acc2[1][jj]);
            acc2[1][jj] = ffma2(kv.u.y, qv1.u.y, acc2[1][jj]);
            acc2[2][jj] = ffma2(kv.u.x, qv2.u.x, acc2[2][jj]);
            acc2[2][jj] = ffma2(kv.u.y, qv2.u.y, acc2[2][jj]);
            acc2[3][jj] = ffma2(kv.u.x, qv3.u.x, acc2[3][jj]);
            acc2[3][jj] = ffma2(kv.u.y, qv3.u.y, acc2[3][jj]);
        }
    }
    #pragma unroll
    for (int qi = 0; qi < 4; qi++)
        #pragma unroll
        for (int jj = 0; jj < JN; jj++)
            sc[qi][JB + jj] = hadd2(acc2[qi][jj]);
}

// -------------------- fused attention -----------------------------------------
__global__ __launch_bounds__(512)
void k_attn(const float* __restrict__ Q, const float* __restrict__ Km,
            const float* __restrict__ Vm) {
    extern __shared__ float sm[];
    float* kv   = sm;            // 352*100
    float* pbuf = sm + 352*100;  // 64*344
    int win = blockIdx.x;
    int tid = threadIdx.x, lane = tid & 31, wp = tid >> 5;
    const float* kw = Km + (size_t)win*WN*CDIM;
    const float* vw = Vm + (size_t)win*WN*CDIM;
    const float* qw = Q  + (size_t)win*WN*CDIM;
    float* ob = g_ot + (size_t)win*WN*CDIM;

    int ws = win >> 6, hs = (win >> 3) & 7, wd = win & 7;
    bool bz = (ws == 7), bh = (hs == 7), bw = (wd == 7);
    const float scale = 0.10206207261596575f;

    unsigned mzm = 0, mhm = 0, mwm = 0, mvm = 0;
    #pragma unroll
    for (int j = 0; j < 11; j++) {
        int m = lane + 32*j;
        if (m < WN) {
            int dzm = m / 49, rm = m % 49, dym = rm / 7, dxm = rm % 7;
            if (dzm < 4) mzm |= 1u << j;
            if (dym < 4) mhm |= 1u << j;
            if (dxm < 4) mwm |= 1u << j;
            mvm |= 1u << j;
        }
    }

    float* myrows = pbuf + wp*4*344;

    for (int chunk = 0; chunk < 6; chunk++) {
        int qbase = chunk*64 + wp*4;
        __syncthreads();
        for (int e = tid; e < WN*CDIM; e += 512)
            kv[(e/96)*100 + (e%96)] = kw[e];
        __syncthreads();

        #pragma unroll
        for (int qi = 0; qi < 4; qi++) {
            int q = qbase + qi;
            if (q < WN) {
                myrows[qi*344 + lane]      = qw[q*96 + lane]      * scale;
                myrows[qi*344 + lane + 32] = qw[q*96 + lane + 32] * scale;
                myrows[qi*344 + lane + 64] = qw[q*96 + lane + 64] * scale;
            }
        }
        __syncwarp();
        float sc[4][11];
        qk_dot<0, 6>(kv, myrows, lane, sc);
        qk_dot<6, 5>(kv, myrows, lane, sc);
        __syncwarp();
        #pragma unroll
        for (int qi = 0; qi < 4; qi++) {
            int q = qbase + qi;
            if (q >= WN) break;
            int dzq = q / 49, rq = q % 49, dyq = rq / 7, dxq = rq % 7;
            bool gz = dzq < 4, gh = dyq < 4, gw = dxq < 4;
            float mx = -1e30f;
            #pragma unroll
            for (int j = 0; j < 11; j++) {
                float v;
                if (mvm & (1u << j)) {
                    bool same = (!bz || (gz == ((mzm >> j) & 1))) &&
                                (!bh || (gh == ((mhm >> j) & 1))) &&
                                (!bw || (gw == ((mwm >> j) & 1)));
                    v = sc[qi][j] + (same ? 0.f : -100.f);
                } else v = -1e30f;
                sc[qi][j] = v;
                mx = fmaxf(mx, v);
            }
            #pragma unroll
            for (int o = 16; o; o >>= 1) mx = fmaxf(mx, __shfl_xor_sync(0xffffffffu, mx, o));
            float ssum = 0.f;
            #pragma unroll
            for (int j = 0; j < 11; j++) { sc[qi][j] = __expf(sc[qi][j] - mx); ssum += sc[qi][j]; }
            #pragma unroll
            for (int o = 16; o; o >>= 1) ssum += __shfl_xor_sync(0xffffffffu, ssum, o);
            float rinv = 1.f / ssum;
            #pragma unroll
            for (int j = 0; j < 11; j++) {
                int m = lane + 32*j;
                if (m < WN) myrows[qi*344 + m] = sc[qi][j] * rinv;
            }
        }
        if (lane < 4) myrows[lane*344 + 343] = 0.f;
        __syncthreads();

        for (int e = tid; e < WN*CDIM; e += 512)
            kv[(e/96)*100 + (e%96)] = vw[e];
        for (int e = tid; e < 9*100; e += 512)
            kv[343*100 + e] = 0.f;
        __syncthreads();

        u64 acc2[4][3] = {};
        #pragma unroll 2
        for (int mi = 0; mi < 344; mi += 2) {
            u64 v0 = pack2(kv[mi*100 + lane],      kv[mi*100 + 100 + lane]);
            u64 v1 = pack2(kv[mi*100 + lane + 32], kv[mi*100 + 132 + lane]);
            u64 v2 = pack2(kv[mi*100 + lane + 64], kv[mi*100 + 164 + lane]);
            #pragma unroll
            for (int qi = 0; qi < 4; qi++) {
                u64 pp = *(const u64*)(myrows + qi*344 + mi);
                acc2[qi][0] = ffma2(pp, v0, acc2[qi][0]);
                acc2[qi][1] = ffma2(pp, v1, acc2[qi][1]);
                acc2[qi][2] = ffma2(pp, v2, acc2[qi][2]);
            }
        }
        #pragma unroll
        for (int qi = 0; qi < 4; qi++) {
            myrows[ lane      *4 + qi] = hadd2(acc2[qi][0]);
            myrows[(lane + 32)*4 + qi] = hadd2(acc2[qi][1]);
            myrows[(lane + 64)*4 + qi] = hadd2(acc2[qi][2]);
        }
        __syncwarp();
        #pragma unroll
        for (int e = lane; e < 384; e += 32) {
            int c = e >> 2, qi = e & 3;
            int q = qbase + qi;
            if (q < WN) ob[(size_t)c*WN + q] = myrows[e];
        }
    }
}

// -------------------- window-reverse + roll(+3) + residual + LN2 --------------
__global__ __launch_bounds__(256)
void k_resln2(const float* __restrict__ x,
              const float* __restrict__ gg, const float* __restrict__ bb) {
    __shared__ float xs[32*101];
    int p0 = blockIdx.x * 32;
    int tid = threadIdx.x, lane = tid & 31, wp = tid >> 5;
    for (int e = tid; e < 96*32; e += 256) {
        int c = e >> 5, i = e & 31;
        xs[i*101 + c] = x[(size_t)c*NTOK + p0 + i];
    }
    __syncthreads();
    #pragma unroll
    for (int ii = wp; ii < 32; ii += 8) {
        int p = p0 + ii;
        int s = p / 3136, r = p % 3136, h = r / 56, w = r % 56;
        int s2 = (s >= 3) ? s - 3 : s + 53;
        int h2 = (h >= 3) ? h - 3 : h + 53;
        int w2 = (w >= 3) ? w - 3 : w + 53;
        int win = (s2/7)*64 + (h2/7)*8 + (w2/7);
        int np  = (s2%7)*49 + (h2%7)*7 + (w2%7);
        const float* ov = g_ot + (size_t)win*WN*CDIM + np*96;
        float v0 = xs[ii*101 + lane]      + ov[lane];
        float v1 = xs[ii*101 + lane + 32] + ov[lane + 32];
        float v2 = xs[ii*101 + lane + 64] + ov[lane + 64];
        float* xr = g_xres + (size_t)p*CDIM;
        xr[lane] = v0; xr[lane + 32] = v1; xr[lane + 64] = v2;
        float sum = v0 + v1 + v2, sq = v0*v0 + v1*v1 + v2*v2;
        #pragma unroll
        for (int o = 16; o; o >>= 1) {
            sum += __shfl_xor_sync(0xffffffffu, sum, o);
            sq  += __shfl_xor_sync(0xffffffffu, sq, o);
        }
        float mean = sum * (1.f/96.f);
        float var  = sq * (1.f/96.f) - mean*mean;
        float inv  = rsqrtf(var + 1e-5f);
        size_t yo = (size_t)p*CDIM;
        float y0 = (v0 - mean)*inv*gg[lane]      + bb[lane];
        float y1 = (v1 - mean)*inv*gg[lane + 32] + bb[lane + 32];
        float y2 = (v2 - mean)*inv*gg[lane + 64] + bb[lane + 64];
        bsplit(y0, g_l2h[yo + lane],      g_l2l[yo + lane]);
        bsplit(y1, g_l2h[yo + lane + 32], g_l2l[yo + lane + 32]);
        bsplit(y2, g_l2h[yo + lane + 64], g_l2l[yo + lane + 64]);
    }
}

// -------------------- launch ---------------------------------------------------
extern "C" void kernel_launch(void* const* d_in, const int* in_sizes, int n_in,
                              void* d_out, int out_size) {
    const float* x   = (const float*)d_in[0];
    const float* n1g = (const float*)d_in[1];
    const float* n1b = (const float*)d_in[2];
    const float* wq  = (const float*)d_in[3];
    const float* bq  = (const float*)d_in[4];
    const float* wk  = (const float*)d_in[5];
    const float* bk  = (const float*)d_in[6];
    const float* wv  = (const float*)d_in[7];
    const float* bv  = (const float*)d_in[8];
    const float* dqw = (const float*)d_in[9];
    const float* dqb = (const float*)d_in[10];
    const float* dkw = (const float*)d_in[11];
    const float* dkb = (const float*)d_in[12];
    const float* dvw = (const float*)d_in[13];
    const float* dvb = (const float*)d_in[14];
    const float* n2g = (const float*)d_in[15];
    const float* n2b = (const float*)d_in[16];
    const float* f1w = (const float*)d_in[17];
    const float* f1b = (const float*)d_in[18];
    const float* f2w = (const float*)d_in[19];
    const float* f2b = (const float*)d_in[20];
    float* out = (float*)d_out;

    float *pqp, *pkp, *pvp, *pq, *pk, *pv, *pxres, *pbqkv;
    __nv_bfloat16 *pxwh, *pxwl, *pl2h, *pl2l, *phh, *phl, *pwqh, *pwql, *pf1h, *pf1l, *pf2h, *pf2l;
    cudaGetSymbolAddress((void**)&pqp,  g_qp);
    cudaGetSymbolAddress((void**)&pkp,  g_kp);
    cudaGetSymbolAddress((void**)&pvp,  g_vp);
    cudaGetSymbolAddress((void**)&pq,   g_q);
    cudaGetSymbolAddress((void**)&pk,   g_k);
    cudaGetSymbolAddress((void**)&pv,   g_v);
    cudaGetSymbolAddress((void**)&pxres,g_xres);
    cudaGetSymbolAddress((void**)&pbqkv,g_bqkv);
    cudaGetSymbolAddress((void**)&pxwh, g_xwh);
    cudaGetSymbolAddress((void**)&pxwl, g_xwl);
    cudaGetSymbolAddress((void**)&pl2h, g_l2h);
    cudaGetSymbolAddress((void**)&pl2l, g_l2l);
    cudaGetSymbolAddress((void**)&phh,  g_hh);
    cudaGetSymbolAddress((void**)&phl,  g_hl);
    cudaGetSymbolAddress((void**)&pwqh, g_wqh);
    cudaGetSymbolAddress((void**)&pwql, g_wql);
    cudaGetSymbolAddress((void**)&pf1h, g_f1h);
    cudaGetSymbolAddress((void**)&pf1l, g_f1l);
    cudaGetSymbolAddress((void**)&pf2h, g_f2h);
    cudaGetSymbolAddress((void**)&pf2l, g_f2l);

    const int ATTN_SMEM = (352*100 + 64*344) * 4;
    cudaFuncSetAttribute(k_attn, cudaFuncAttributeMaxDynamicSharedMemorySize, ATTN_SMEM);
    cudaFuncSetAttribute(k_tgemm<0>, cudaFuncAttributeMaxDynamicSharedMemorySize, TG_SMEM);
    cudaFuncSetAttribute(k_tgemm<1>, cudaFuncAttributeMaxDynamicSharedMemorySize, TG_SMEM);
    cudaFuncSetAttribute(k_tgemm<2>, cudaFuncAttributeMaxDynamicSharedMemorySize, TG_SMEM);

    k_prep1<<<(3*96*96 + 255)/256, 256>>>(wq, bq, wk, bk, wv, bv);
    k_prep2<<<(HIDD*96 + 255)/256, 256>>>(f1w, f2w);
    k_ln1<<<NTOK/64, 256>>>(x, n1g, n1b);

    // qkv: D = xw @ wqkv^T (+bias), split to 3 buffers
    dim3 gq(NTOK/128, 3);
    k_tgemm<0><<<gq, 256, TG_SMEM>>>(pxwh, pxwl, pwqh, pwql, pbqkv, 96,
                                     pqp, pkp, pvp, nullptr, nullptr, nullptr, nullptr);

    dim3 gdw(NW, 3);
    k_dw<<<gdw, 392>>>(pqp, dqw, dqb, pq);
    k_dw<<<gdw, 392>>>(pkp, dkw, dkb, pk);
    k_dw<<<gdw, 392>>>(pvp, dvw, dvb, pv);

    k_attn<<<NW, 512, ATTN_SMEM>>>(pq, pk, pv);

    k_resln2<<<NTOK/32, 256>>>(x, n2g, n2b);

    // MLP1: GELU(ln2 @ f1w^T + f1b) -> bf16 hi/lo planes
    dim3 g2(NTOK/128, HIDD/96);
    k_tgemm<1><<<g2, 256, TG_SMEM>>>(pl2h, pl2l, pf1h, pf1l, f1b, 96,
                                     nullptr, nullptr, nullptr, phh, phl, nullptr, nullptr);
    // MLP2: out^T = (h @ f2w^T + f2b + xres)
    dim3 g3(NTOK/128, 1);
    k_tgemm<2><<<g3, 256, TG_SMEM>>>(phh, phl, pf2h, pf2l, f2b, HIDD,
                                     nullptr, nullptr, nullptr, nullptr, nullptr, pxres, out);
}

// round 9
// speedup vs baseline: 1.3963x; 1.1870x over previous
#include <cuda_runtime.h>
#include <cuda_bf16.h>
#include <math.h>
#include <stdint.h>

#define NTOK 175616   // 56*56*56
#define CDIM 96
#define NW   512
#define WN   343
#define HIDD 384

typedef unsigned long long u64;
typedef unsigned int u32;
union F4U { float4 f; ulonglong2 u; };

__device__ __forceinline__ u64 ffma2(u64 a, u64 b, u64 c) {
    u64 d; asm("fma.rn.f32x2 %0, %1, %2, %3;" : "=l"(d) : "l"(a), "l"(b), "l"(c));
    return d;
}
__device__ __forceinline__ void bsplit(float v, __nv_bfloat16& h, __nv_bfloat16& l) {
    h = __float2bfloat16_rn(v);
    l = __float2bfloat16_rn(v - __bfloat162float(h));
}
__device__ __forceinline__ u32 pack_bf(__nv_bfloat16 a, __nv_bfloat16 b) {
    return (u32)__bfloat16_as_ushort(a) | ((u32)__bfloat16_as_ushort(b) << 16);
}
__device__ __forceinline__ float gelu_f(float v) {
    return 0.5f * v * (1.f + erff(v * 0.70710678118654752f));
}
__device__ __forceinline__ void mma16816(float* d, const u32* a, u32 b0, u32 b1) {
    asm volatile("mma.sync.aligned.m16n8k16.row.col.f32.bf16.bf16.f32 "
                 "{%0,%1,%2,%3}, {%4,%5,%6,%7}, {%8,%9}, {%0,%1,%2,%3};"
                 : "+f"(d[0]), "+f"(d[1]), "+f"(d[2]), "+f"(d[3])
                 : "r"(a[0]), "r"(a[1]), "r"(a[2]), "r"(a[3]), "r"(b0), "r"(b1));
}
__device__ __forceinline__ void ldmx4(u32* r, const __nv_bfloat16* p) {
    u32 addr = (u32)__cvta_generic_to_shared(p);
    asm volatile("ldmatrix.sync.aligned.m8n8.x4.shared.b16 {%0,%1,%2,%3}, [%4];"
                 : "=r"(r[0]), "=r"(r[1]), "=r"(r[2]), "=r"(r[3]) : "r"(addr));
}
__device__ __forceinline__ void ldmx4t(u32* r, const __nv_bfloat16* p) {
    u32 addr = (u32)__cvta_generic_to_shared(p);
    asm volatile("ldmatrix.sync.aligned.m8n8.x4.trans.shared.b16 {%0,%1,%2,%3}, [%4];"
                 : "=r"(r[0]), "=r"(r[1]), "=r"(r[2]), "=r"(r[3]) : "r"(addr));
}
__device__ __forceinline__ void ldmx2t(u32* r, const __nv_bfloat16* p) {
    u32 addr = (u32)__cvta_generic_to_shared(p);
    asm volatile("ldmatrix.sync.aligned.m8n8.x2.trans.shared.b16 {%0,%1}, [%2];"
                 : "=r"(r[0]), "=r"(r[1]) : "r"(addr));
}

// -------------------- scratch (device globals) -------------------------------
__device__ __nv_bfloat16 g_xwh[(size_t)NTOK*CDIM], g_xwl[(size_t)NTOK*CDIM];
__device__ float g_qp [(size_t)NTOK*CDIM];
__device__ float g_kp [(size_t)NTOK*CDIM];
__device__ float g_vp [(size_t)NTOK*CDIM];
__device__ __nv_bfloat16 g_qh[(size_t)NTOK*CDIM], g_ql[(size_t)NTOK*CDIM];
__device__ __nv_bfloat16 g_kh[(size_t)NTOK*CDIM], g_kl[(size_t)NTOK*CDIM];
__device__ __nv_bfloat16 g_vh[(size_t)NTOK*CDIM], g_vl[(size_t)NTOK*CDIM];
__device__ float g_ot [(size_t)NTOK*CDIM];   // attention out, axis-mixed: flat = c*343 + n
__device__ float g_xres[(size_t)NTOK*CDIM];
__device__ __nv_bfloat16 g_l2h[(size_t)NTOK*CDIM], g_l2l[(size_t)NTOK*CDIM];
__device__ __nv_bfloat16 g_hh[(size_t)NTOK*HIDD], g_hl[(size_t)NTOK*HIDD];
__device__ __nv_bfloat16 g_wqh[288*96], g_wql[288*96];
__device__ __nv_bfloat16 g_f1h[HIDD*96], g_f1l[HIDD*96];
__device__ __nv_bfloat16 g_f2h[96*HIDD], g_f2l[96*HIDD];
__device__ float g_bqkv[288];

// -------------------- weight prep --------------------------------------------
__global__ void k_prep1(const float* __restrict__ wq, const float* __restrict__ bq,
                        const float* __restrict__ wk, const float* __restrict__ bk,
                        const float* __restrict__ wv, const float* __restrict__ bv) {
    int i = blockIdx.x * 256 + threadIdx.x;
    if (i < 3*96*96) {
        int t = i / 9216, r = i % 9216;
        float v = (t == 0) ? wq[r] : (t == 1) ? wk[r] : wv[r];
        bsplit(v, g_wqh[i], g_wql[i]);
    }
    if (i < 288) {
        int t = i / 96, r = i % 96;
        g_bqkv[i] = (t == 0) ? bq[r] : (t == 1) ? bk[r] : bv[r];
    }
}
__global__ void k_prep2(const float* __restrict__ f1w, const float* __restrict__ f2w) {
    int i = blockIdx.x * 256 + threadIdx.x;
    if (i < HIDD*96) {
        bsplit(f1w[i], g_f1h[i], g_f1l[i]);
        bsplit(f2w[i], g_f2h[i], g_f2l[i]);
    }
}

// -------------------- LN1 + roll(-3) + window partition -----------------------
__global__ __launch_bounds__(256)
void k_ln1(const float* __restrict__ x,
           const float* __restrict__ gg, const float* __restrict__ bb) {
    __shared__ float xs[64*101];
    int p0 = blockIdx.x * 64;
    int tid = threadIdx.x, lane = tid & 31, wp = tid >> 5;
    for (int e = tid; e < 96*64; e += 256) {
        int c = e >> 6, i = e & 63;
        xs[i*101 + c] = x[(size_t)c*NTOK + p0 + i];
    }
    __syncthreads();
    #pragma unroll
    for (int ii = wp; ii < 64; ii += 8) {
        int p = p0 + ii;
        int s = p / 3136, r = p % 3136, h = r / 56, w = r % 56;
        int s2 = (s >= 3) ? s - 3 : s + 53;
        int h2 = (h >= 3) ? h - 3 : h + 53;
        int w2 = (w >= 3) ? w - 3 : w + 53;
        int win = (s2/7)*64 + (h2/7)*8 + (w2/7);
        int t   = (s2%7)*49 + (h2%7)*7 + (w2%7);
        float v0 = xs[ii*101 + lane];
        float v1 = xs[ii*101 + lane + 32];
        float v2 = xs[ii*101 + lane + 64];
        float sum = v0 + v1 + v2, sq = v0*v0 + v1*v1 + v2*v2;
        #pragma unroll
        for (int o = 16; o; o >>= 1) {
            sum += __shfl_xor_sync(0xffffffffu, sum, o);
            sq  += __shfl_xor_sync(0xffffffffu, sq, o);
        }
        float mean = sum * (1.f/96.f);
        float var  = sq * (1.f/96.f) - mean*mean;
        float inv  = rsqrtf(var + 1e-5f);
        size_t ob = ((size_t)win*WN + t)*CDIM;
        float y0 = (v0 - mean)*inv*gg[lane]      + bb[lane];
        float y1 = (v1 - mean)*inv*gg[lane + 32] + bb[lane + 32];
        float y2 = (v2 - mean)*inv*gg[lane + 64] + bb[lane + 64];
        bsplit(y0, g_xwh[ob + lane],      g_xwl[ob + lane]);
        bsplit(y1, g_xwh[ob + lane + 32], g_xwl[ob + lane + 32]);
        bsplit(y2, g_xwh[ob + lane + 64], g_xwl[ob + lane + 64]);
    }
}

// -------------------- tensor-core GEMM (bf16 split, mma.sync + ldmatrix) -----
#define SA_STRIDE 104
#define TG_A_HI 0
#define TG_A_LO (128*104)          // bf16 units
#define TG_B_HI (2*128*104)
#define TG_B_LO (2*128*104 + 96*104)
#define TG_SMEM ((2*128*104 + 2*96*104) * 2)   // 93184 bytes

template<int EPI>
__global__ __launch_bounds__(256, 2)
void k_tgemm(const __nv_bfloat16* __restrict__ Ah, const __nv_bfloat16* __restrict__ Al,
             const __nv_bfloat16* __restrict__ Wh, const __nv_bfloat16* __restrict__ Wl,
             const float* __restrict__ bias, int K,
             float* __restrict__ O0, float* __restrict__ O1, float* __restrict__ O2,
             __nv_bfloat16* __restrict__ Oh, __nv_bfloat16* __restrict__ Ol,
             const float* __restrict__ Res, float* __restrict__ OutT) {
    extern __shared__ char smemc[];
    __nv_bfloat16* sA = (__nv_bfloat16*)smemc;
    int tid = threadIdx.x, lane = tid & 31, wid = tid >> 5;
    int g = lane >> 2, tg = lane & 3;
    int bm = blockIdx.x * 128, bn = blockIdx.y * 96;
    int warpM = (wid & 3) * 32, warpN = (wid >> 2) * 48;
    int lr = lane & 15;
    int lc = (lane & 16) ? 8 : 0;

    float acc[2][6][4];
    #pragma unroll
    for (int mt = 0; mt < 2; mt++)
        #pragma unroll
        for (int nt = 0; nt < 6; nt++)
            #pragma unroll
            for (int i = 0; i < 4; i++) acc[mt][nt][i] = 0.f;

    int nch = K / 96;
    for (int kc = 0; kc < nch; kc++) {
        const __nv_bfloat16* pAh = Ah + (size_t)bm*K + kc*96;
        const __nv_bfloat16* pAl = Al + (size_t)bm*K + kc*96;
        for (int e = tid; e < 128*24; e += 256) {
            int r = e / 24, c4 = e % 24;
            *(uint2*)(sA + TG_A_HI + r*SA_STRIDE + c4*4) = *(const uint2*)(pAh + (size_t)r*K + c4*4);
            *(uint2*)(sA + TG_A_LO + r*SA_STRIDE + c4*4) = *(const uint2*)(pAl + (size_t)r*K + c4*4);
        }
        const __nv_bfloat16* pWh = Wh + (size_t)bn*K + kc*96;
        const __nv_bfloat16* pWl = Wl + (size_t)bn*K + kc*96;
        for (int e = tid; e < 96*24; e += 256) {
            int r = e / 24, c4 = e % 24;
            *(uint2*)(sA + TG_B_HI + r*SA_STRIDE + c4*4) = *(const uint2*)(pWh + (size_t)r*K + c4*4);
            *(uint2*)(sA + TG_B_LO + r*SA_STRIDE + c4*4) = *(const uint2*)(pWl + (size_t)r*K + c4*4);
        }
        __syncthreads();

        #pragma unroll
        for (int ks = 0; ks < 6; ks++) {
            int k0 = ks * 16;
            u32 ah[2][4], al_[2][4];
            #pragma unroll
            for (int mt = 0; mt < 2; mt++) {
                int ro = (warpM + mt*16 + lr)*SA_STRIDE + k0 + lc;
                ldmx4(ah[mt],  sA + TG_A_HI + ro);
                ldmx4(al_[mt], sA + TG_A_LO + ro);
            }
            u32 bh[3][4], bl[3][4];
            #pragma unroll
            for (int np = 0; np < 3; np++) {
                int ro = (warpN + np*16 + lr)*SA_STRIDE + k0 + lc;
                ldmx4(bh[np], sA + TG_B_HI + ro);
                ldmx4(bl[np], sA + TG_B_LO + ro);
            }
            #pragma unroll
            for (int np = 0; np < 3; np++) {
                #pragma unroll
                for (int mt = 0; mt < 2; mt++) {
                    mma16816(acc[mt][2*np],   ah[mt],  bh[np][0], bh[np][2]);
                    mma16816(acc[mt][2*np+1], ah[mt],  bh[np][1], bh[np][3]);
                    mma16816(acc[mt][2*np],   ah[mt],  bl[np][0], bl[np][2]);
                    mma16816(acc[mt][2*np+1], ah[mt],  bl[np][1], bl[np][3]);
                    mma16816(acc[mt][2*np],   al_[mt], bh[np][0], bh[np][2]);
                    mma16816(acc[mt][2*np+1], al_[mt], bh[np][1], bh[np][3]);
                }
            }
        }
        __syncthreads();
    }

    if (EPI == 0) {
        float* O = (blockIdx.y == 0) ? O0 : (blockIdx.y == 1) ? O1 : O2;
        #pragma unroll
        for (int mt = 0; mt < 2; mt++) {
            int r0 = bm + warpM + mt*16 + g;
            #pragma unroll
            for (int nt = 0; nt < 6; nt++) {
                int c = warpN + nt*8 + 2*tg;
                float b0 = bias[bn + c], b1 = bias[bn + c + 1];
                *(float2*)(O + (size_t)r0*96 + c)       = make_float2(acc[mt][nt][0] + b0, acc[mt][nt][1] + b1);
                *(float2*)(O + (size_t)(r0 + 8)*96 + c) = make_float2(acc[mt][nt][2] + b0, acc[mt][nt][3] + b1);
            }
        }
    } else if (EPI == 1) {
        #pragma unroll
        for (int mt = 0; mt < 2; mt++) {
            int r0 = bm + warpM + mt*16 + g;
            #pragma unroll
            for (int nt = 0; nt < 6; nt++) {
                int c = warpN + nt*8 + 2*tg;
                float b0 = bias[bn + c], b1 = bias[bn + c + 1];
                #pragma unroll
                for (int hrow = 0; hrow < 2; hrow++) {
                    int row = r0 + hrow*8;
                    float v0 = gelu_f(acc[mt][nt][2*hrow]   + b0);
                    float v1 = gelu_f(acc[mt][nt][2*hrow+1] + b1);
                    __nv_bfloat16 h0, l0, h1, l1;
                    bsplit(v0, h0, l0);
                    bsplit(v1, h1, l1);
                    *(u32*)(Oh + (size_t)row*HIDD + bn + c) = pack_bf(h0, h1);
                    *(u32*)(Ol + (size_t)row*HIDD + bn + c) = pack_bf(l0, l1);
                }
            }
        }
    } else {
        float* st = (float*)smemc;    // 96 cols x 132 rows
        #pragma unroll
        for (int mt = 0; mt < 2; mt++) {
            int rl = warpM + mt*16 + g;
            #pragma unroll
            for (int nt = 0; nt < 6; nt++) {
                int c = warpN + nt*8 + 2*tg;
                float b0 = bias[c], b1 = bias[c + 1];
                #pragma unroll
                for (int hrow = 0; hrow < 2; hrow++) {
                    int row = rl + hrow*8;
                    const float* rr = Res + (size_t)(bm + row)*96;
                    st[(c)  *132 + row] = acc[mt][nt][2*hrow]   + b0 + rr[c];
                    st[(c+1)*132 + row] = acc[mt][nt][2*hrow+1] + b1 + rr[c+1];
                }
            }
        }
        __syncthreads();
        for (int e = tid; e < 96*128; e += 256) {
            int col = e >> 7, r = e & 127;
            OutT[(size_t)col*NTOK + bm + r] = st[col*132 + r];
        }
    }
}

// -------------------- depthwise 3x3x3 (packed, bf16-split output) -------------
__global__ __launch_bounds__(392, 2)
void k_dw(const float* __restrict__ In, const float* __restrict__ Wt,
          const float* __restrict__ Bi,
          __nv_bfloat16* __restrict__ OutH, __nv_bfloat16* __restrict__ OutL) {
    __shared__ float sin_[WN*32];
    __shared__ float wsm[27*32];
    int win = blockIdx.x;
    int c0 = blockIdx.y * 32;
    int tid = threadIdx.x;
    const float* inw = In + (size_t)win*WN*CDIM + c0;
    for (int e = tid; e < WN*8; e += 392) {
        int t = e >> 3, c4 = e & 7;
        *(float4*)(sin_ + t*32 + c4*4) = *(const float4*)(inw + t*96 + c4*4);
    }
    for (int e = tid; e < 27*32; e += 392) {
        int k = e >> 5, cc = e & 31;
        wsm[k*32 + cc] = Wt[(c0 + cc)*27 + k];
    }
    __syncthreads();

    int g = tid & 7, dy = (tid >> 3) % 7, dz = tid / 56;
    int cc = g * 4;
    F4U bias4; bias4.f = *(const float4*)(Bi + c0 + cc);
    u64 ax[7], ay[7];
    #pragma unroll
    for (int x = 0; x < 7; x++) { ax[x] = bias4.u.x; ay[x] = bias4.u.y; }

    #pragma unroll
    for (int kd = 0; kd < 3; kd++) {
        int nz = dz + kd - 1;
        if ((unsigned)nz >= 7u) continue;
        #pragma unroll
        for (int kh = 0; kh < 3; kh++) {
            int ny = dy + kh - 1;
            if ((unsigned)ny >= 7u) continue;
            const float* row = sin_ + (nz*49 + ny*7)*32 + cc;
            F4U iv[7];
            #pragma unroll
            for (int x = 0; x < 7; x++) iv[x].f = *(const float4*)(row + x*32);
            const float* wp_ = wsm + (kd*9 + kh*3)*32 + cc;
            F4U w0, w1, w2;
            w0.f = *(const float4*)(wp_);
            w1.f = *(const float4*)(wp_ + 32);
            w2.f = *(const float4*)(wp_ + 64);
            #pragma unroll
            for (int x = 1; x < 7; x++) {
                ax[x] = ffma2(w0.u.x, iv[x-1].u.x, ax[x]);
                ay[x] = ffma2(w0.u.y, iv[x-1].u.y, ay[x]);
            }
            #pragma unroll
            for (int x = 0; x < 7; x++) {
                ax[x] = ffma2(w1.u.x, iv[x].u.x, ax[x]);
                ay[x] = ffma2(w1.u.y, iv[x].u.y, ay[x]);
            }
            #pragma unroll
            for (int x = 0; x < 6; x++) {
                ax[x] = ffma2(w2.u.x, iv[x+1].u.x, ax[x]);
                ay[x] = ffma2(w2.u.y, iv[x+1].u.y, ay[x]);
            }
        }
    }

    size_t ob = (size_t)win*WN*CDIM + (size_t)(dz*49 + dy*7)*96 + c0 + cc;
    #pragma unroll
    for (int x = 0; x < 7; x++) {
        F4U o; o.u.x = ax[x]; o.u.y = ay[x];
        __nv_bfloat16 h0,l0,h1,l1,h2,l2,h3,l3;
        bsplit(o.f.x, h0, l0); bsplit(o.f.y, h1, l1);
        bsplit(o.f.z, h2, l2); bsplit(o.f.w, h3, l3);
        uint2 vh = make_uint2(pack_bf(h0,h1), pack_bf(h2,h3));
        uint2 vl = make_uint2(pack_bf(l0,l1), pack_bf(l2,l3));
        *(uint2*)(OutH + ob + (size_t)x*96) = vh;
        *(uint2*)(OutL + ob + (size_t)x*96) = vl;
    }
}

// -------------------- tensor-core fused attention -----------------------------
// One block / window, 256 thr (8 warps). q-chunks of 64.
// smem byte map (overlap-scheduled):
//   [0..149760)       K planes (360 rows x 104 bf16 x 2)       [S phase]
//   [149760..176384)  Q planes (64 x 104 bf16 x 2)             [S phase]
//   [0..90112)        S fp32 (64 x 352)                        [softmax]
//   [92160..184320)   P planes (64 x 360 bf16 x 2)             [softmax->PV]
//   [0..73216)        V half planes (176 x 104 bf16 x 2)       [PV]
//   [0..25344)        O staging fp32 (96 x 66)                 [store]
#define AB_KH 0
#define AB_KL 74880
#define AB_QH 149760
#define AB_QL 163072
#define AB_PH 92160
#define AB_PL 138240
#define AB_VH 0
#define AB_VL 36608
#define AT_SMEM 184320

__global__ __launch_bounds__(256, 1)
void k_attn(const __nv_bfloat16* __restrict__ Qh, const __nv_bfloat16* __restrict__ Ql,
            const __nv_bfloat16* __restrict__ Kh, const __nv_bfloat16* __restrict__ Kl,
            const __nv_bfloat16* __restrict__ Vh, const __nv_bfloat16* __restrict__ Vl) {
    extern __shared__ char smb[];
    __nv_bfloat16* kh_s = (__nv_bfloat16*)(smb + AB_KH);
    __nv_bfloat16* kl_s = (__nv_bfloat16*)(smb + AB_KL);
    __nv_bfloat16* qh_s = (__nv_bfloat16*)(smb + AB_QH);
    __nv_bfloat16* ql_s = (__nv_bfloat16*)(smb + AB_QL);
    __nv_bfloat16* ph_s = (__nv_bfloat16*)(smb + AB_PH);
    __nv_bfloat16* pl_s = (__nv_bfloat16*)(smb + AB_PL);
    __nv_bfloat16* vh_s = (__nv_bfloat16*)(smb + AB_VH);
    __nv_bfloat16* vl_s = (__nv_bfloat16*)(smb + AB_VL);
    float* S_s = (float*)smb;
    float* O_s = (float*)smb;

    int win = blockIdx.x;
    int tid = threadIdx.x, lane = tid & 31, wp = tid >> 5;
    int g = lane >> 2, tg = lane & 3;
    int lr = lane & 15, lc = (lane & 16) ? 8 : 0;
    int wm = wp & 1, wn = wp >> 1;      // 2 x 4 warp grid

    const __nv_bfloat16* gqh = Qh + (size_t)win*WN*CDIM;
    const __nv_bfloat16* gql = Ql + (size_t)win*WN*CDIM;
    const __nv_bfloat16* gkh = Kh + (size_t)win*WN*CDIM;
    const __nv_bfloat16* gkl = Kl + (size_t)win*WN*CDIM;
    const __nv_bfloat16* gvh = Vh + (size_t)win*WN*CDIM;
    const __nv_bfloat16* gvl = Vl + (size_t)win*WN*CDIM;
    float* ob = g_ot + (size_t)win*WN*CDIM;

    int ws = win >> 6, hs = (win >> 3) & 7, wd = win & 7;
    bool bz = (ws == 7), bh_ = (hs == 7), bw = (wd == 7);
    const float scale = 0.10206207261596575f;   // 1/sqrt(96)

    unsigned mzm = 0, mhm = 0, mwm = 0, mvm = 0;
    #pragma unroll
    for (int j = 0; j < 11; j++) {
        int m = lane + 32*j;
        if (m < WN) {
            int dzm = m / 49, rm = m % 49, dym = rm / 7, dxm = rm % 7;
            if (dzm < 4) mzm |= 1u << j;
            if (dym < 4) mhm |= 1u << j;
            if (dxm < 4) mwm |= 1u << j;
            mvm |= 1u << j;
        }
    }

    for (int chunk = 0; chunk < 6; chunk++) {
        int qbase = chunk * 64;
        __syncthreads();
        // ---- load K planes (343 rows; pad rows stale, masked later) ----
        for (int e = tid; e < 343*24; e += 256) {
            int r = e / 24, c4 = e % 24;
            *(uint2*)(kh_s + r*104 + c4*4) = *(const uint2*)(gkh + (size_t)r*96 + c4*4);
            *(uint2*)(kl_s + r*104 + c4*4) = *(const uint2*)(gkl + (size_t)r*96 + c4*4);
        }
        // ---- stage Q chunk (zero pad rows) ----
        for (int e = tid; e < 64*24; e += 256) {
            int r = e / 24, c4 = e % 24;
            int q = qbase + r;
            uint2 vh = make_uint2(0u, 0u), vl = make_uint2(0u, 0u);
            if (q < WN) {
                vh = *(const uint2*)(gqh + (size_t)q*96 + c4*4);
                vl = *(const uint2*)(gql + (size_t)q*96 + c4*4);
            }
            *(uint2*)(qh_s + r*104 + c4*4) = vh;
            *(uint2*)(ql_s + r*104 + c4*4) = vl;
        }
        __syncthreads();

        // ---- phase S: S[64x352] = Q Kt (3-pass split) ----
        float sacc[2][11][4];
        #pragma unroll
        for (int rt = 0; rt < 2; rt++)
            #pragma unroll
            for (int ct = 0; ct < 11; ct++)
                #pragma unroll
                for (int i = 0; i < 4; i++) sacc[rt][ct][i] = 0.f;

        #pragma unroll
        for (int ks = 0; ks < 6; ks++) {
            int k0 = ks * 16;
            u32 aqh[2][4], aql[2][4];
            #pragma unroll
            for (int rt = 0; rt < 2; rt++) {
                int ro = (wm*32 + rt*16 + lr)*104 + k0 + lc;
                ldmx4(aqh[rt], qh_s + ro);
                ldmx4(aql[rt], ql_s + ro);
            }
            #pragma unroll
            for (int bg = 0; bg < 6; bg++) {
                int n0 = wn*88 + bg*16;
                u32 bh[4], bl[4];
                int ro = (n0 + lr)*104 + k0 + lc;
                ldmx4(bh, kh_s + ro);
                ldmx4(bl, kl_s + ro);
                #pragma unroll
                for (int rt = 0; rt < 2; rt++) {
                    mma16816(sacc[rt][2*bg], aqh[rt], bh[0], bh[2]);
                    mma16816(sacc[rt][2*bg], aqh[rt], bl[0], bl[2]);
                    mma16816(sacc[rt][2*bg], aql[rt], bh[0], bh[2]);
                    if (bg < 5) {
                        mma16816(sacc[rt][2*bg+1], aqh[rt], bh[1], bh[3]);
                        mma16816(sacc[rt][2*bg+1], aqh[rt], bl[1], bl[3]);
                        mma16816(sacc[rt][2*bg+1], aql[rt], bh[1], bh[3]);
                    }
                }
            }
        }
        __syncthreads();   // K dead; S region reuses it

        // ---- store S fragments ----
        #pragma unroll
        for (int rt = 0; rt < 2; rt++) {
            int row = wm*32 + rt*16 + g;
            #pragma unroll
            for (int ct = 0; ct < 11; ct++) {
                int col = wn*88 + ct*8 + 2*tg;
                *(float2*)(S_s + row*352 + col)       = make_float2(sacc[rt][ct][0], sacc[rt][ct][1]);
                *(float2*)(S_s + (row + 8)*352 + col) = make_float2(sacc[rt][ct][2], sacc[rt][ct][3]);
            }
        }
        __syncthreads();

        // ---- softmax + P split planes ----
        #pragma unroll
        for (int rr = 0; rr < 8; rr++) {
            int qr = wp*8 + rr;
            int q = qbase + qr;
            __nv_bfloat16* ph = ph_s + qr*360;
            __nv_bfloat16* pl = pl_s + qr*360;
            if (q < WN) {
                int dzq = q / 49, rq = q % 49, dyq = rq / 7, dxq = rq % 7;
                bool gz = dzq < 4, gh = dyq < 4, gw = dxq < 4;
                float sc[11];
                float mx = -1e30f;
                #pragma unroll
                for (int j = 0; j < 11; j++) {
                    float v;
                    if (mvm & (1u << j)) {
                        bool same = (!bz  || (gz == ((mzm >> j) & 1))) &&
                                    (!bh_ || (gh == ((mhm >> j) & 1))) &&
                                    (!bw  || (gw == ((mwm >> j) & 1)));
                        v = S_s[qr*352 + lane + 32*j] * scale + (same ? 0.f : -100.f);
                    } else v = -1e30f;
                    sc[j] = v;
                    mx = fmaxf(mx, v);
                }
                #pragma unroll
                for (int o = 16; o; o >>= 1) mx = fmaxf(mx, __shfl_xor_sync(0xffffffffu, mx, o));
                float ssum = 0.f;
                #pragma unroll
                for (int j = 0; j < 11; j++) { sc[j] = __expf(sc[j] - mx); ssum += sc[j]; }
                #pragma unroll
                for (int o = 16; o; o >>= 1) ssum += __shfl_xor_sync(0xffffffffu, ssum, o);
                float rinv = 1.f / ssum;
                #pragma unroll
                for (int j = 0; j < 11; j++) {
                    int m = lane + 32*j;
                    __nv_bfloat16 h, l;
                    if (mvm & (1u << j)) bsplit(sc[j] * rinv, h, l);
                    else { h = __float2bfloat16(0.f); l = h; }
                    ph[m] = h; pl[m] = l;
                }
            } else {
                __nv_bfloat16 z = __float2bfloat16(0.f);
                #pragma unroll
                for (int j = 0; j < 11; j++) { ph[lane + 32*j] = z; pl[lane + 32*j] = z; }
            }
            if (lane < 8) {
                __nv_bfloat16 z = __float2bfloat16(0.f);
                ph[352 + lane] = z; pl[352 + lane] = z;
            }
        }

        // ---- phase PV: O[64x96] = P V (two V halves) ----
        float oacc[2][3][4];
        #pragma unroll
        for (int rt = 0; rt < 2; rt++)
            #pragma unroll
            for (int ct = 0; ct < 3; ct++)
                #pragma unroll
                for (int i = 0; i < 4; i++) oacc[rt][ct][i] = 0.f;

        for (int hh = 0; hh < 2; hh++) {
            __syncthreads();   // S/prev-V reads done
            for (int e = tid; e < 176*24; e += 256) {
                int r = e / 24, c4 = e % 24;
                int m = hh*176 + r;
                uint2 vh = make_uint2(0u, 0u), vl = make_uint2(0u, 0u);
                if (m < WN) {
                    vh = *(const uint2*)(gvh + (size_t)m*96 + c4*4);
                    vl = *(const uint2*)(gvl + (size_t)m*96 + c4*4);
                }
                *(uint2*)(vh_s + r*104 + c4*4) = vh;
                *(uint2*)(vl_s + r*104 + c4*4) = vl;
            }
            __syncthreads();

            #pragma unroll
            for (int s = 0; s < 11; s++) {
                int kg = hh*176 + s*16;    // P col
                int kv = s*16;             // local V row
                u32 aph[2][4], apl[2][4];
                #pragma unroll
                for (int rt = 0; rt < 2; rt++) {
                    int ro = (wm*32 + rt*16 + lr)*360 + kg + lc;
                    ldmx4(aph[rt], ph_s + ro);
                    ldmx4(apl[rt], pl_s + ro);
                }
                int n0 = wn*24;
                u32 bvh[6], bvl[6];
                {
                    int ro = (kv + lr)*104 + n0 + lc;
                    ldmx4t(bvh, vh_s + ro);
                    ldmx4t(bvl, vl_s + ro);
                    int ro2 = (kv + lr)*104 + n0 + 16;
                    ldmx2t(bvh + 4, vh_s + ro2);
                    ldmx2t(bvl + 4, vl_s + ro2);
                }
                #pragma unroll
                for (int rt = 0; rt < 2; rt++) {
                    #pragma unroll
                    for (int ct = 0; ct < 3; ct++) {
                        u32 b0h = bvh[2*ct], b1h = bvh[2*ct+1];
                        u32 b0l = bvl[2*ct], b1l = bvl[2*ct+1];
                        mma16816(oacc[rt][ct], aph[rt], b0h, b1h);
                        mma16816(oacc[rt][ct], aph[rt], b0l, b1l);
                        mma16816(oacc[rt][ct], apl[rt], b0h, b1h);
                    }
                }
            }
        }
        __syncthreads();   // PV done; V region dead -> O staging

        #pragma unroll
        for (int rt = 0; rt < 2; rt++) {
            int row = wm*32 + rt*16 + g;
            #pragma unroll
            for (int ct = 0; ct < 3; ct++) {
                int col = wn*24 + ct*8 + 2*tg;
                O_s[(col)  *66 + row]     = oacc[rt][ct][0];
                O_s[(col+1)*66 + row]     = oacc[rt][ct][1];
                O_s[(col)  *66 + row + 8] = oacc[rt][ct][2];
                O_s[(col+1)*66 + row + 8] = oacc[rt][ct][3];
            }
        }
        __syncthreads();
        for (int e = tid; e < 96*64; e += 256) {
            int c = e >> 6, i = e & 63;
            int q = qbase + i;
            if (q < WN) ob[(size_t)c*WN + q] = O_s[c*66 + i];
        }
    }
}

// -------------------- window-reverse + roll(+3) + residual + LN2 --------------
__global__ __launch_bounds__(256)
void k_resln2(const float* __restrict__ x,
              const float* __restrict__ gg, const float* __restrict__ bb) {
    __shared__ float xs[32*101];
    int p0 = blockIdx.x * 32;
    int tid = threadIdx.x, lane = tid & 31, wp = tid >> 5;
    for (int e = tid; e < 96*32; e += 256) {
        int c = e >> 5, i = e & 31;
        xs[i*101 + c] = x[(size_t)c*NTOK + p0 + i];
    }
    __syncthreads();
    #pragma unroll
    for (int ii = wp; ii < 32; ii += 8) {
        int p = p0 + ii;
        int s = p / 3136, r = p % 3136, h = r / 56, w = r % 56;
        int s2 = (s >= 3) ? s - 3 : s + 53;
        int h2 = (h >= 3) ? h - 3 : h + 53;
        int w2 = (w >= 3) ? w - 3 : w + 53;
        int win = (s2/7)*64 + (h2/7)*8 + (w2/7);
        int np  = (s2%7)*49 + (h2%7)*7 + (w2%7);
        const float* ov = g_ot + (size_t)win*WN*CDIM + np*96;
        float v0 = xs[ii*101 + lane]      + ov[lane];
        float v1 = xs[ii*101 + lane + 32] + ov[lane + 32];
        float v2 = xs[ii*101 + lane + 64] + ov[lane + 64];
        float* xr = g_xres + (size_t)p*CDIM;
        xr[lane] = v0; xr[lane + 32] = v1; xr[lane + 64] = v2;
        float sum = v0 + v1 + v2, sq = v0*v0 + v1*v1 + v2*v2;
        #pragma unroll
        for (int o = 16; o; o >>= 1) {
            sum += __shfl_xor_sync(0xffffffffu, sum, o);
            sq  += __shfl_xor_sync(0xffffffffu, sq, o);
        }
        float mean = sum * (1.f/96.f);
        float var  = sq * (1.f/96.f) - mean*mean;
        float inv  = rsqrtf(var + 1e-5f);
        size_t yo = (size_t)p*CDIM;
        float y0 = (v0 - mean)*inv*gg[lane]      + bb[lane];
        float y1 = (v1 - mean)*inv*gg[lane + 32] + bb[lane + 32];
        float y2 = (v2 - mean)*inv*gg[lane + 64] + bb[lane + 64];
        bsplit(y0, g_l2h[yo + lane],      g_l2l[yo + lane]);
        bsplit(y1, g_l2h[yo + lane + 32], g_l2l[yo + lane + 32]);
        bsplit(y2, g_l2h[yo + lane + 64], g_l2l[yo + lane + 64]);
    }
}

// -------------------- launch ---------------------------------------------------
extern "C" void kernel_launch(void* const* d_in, const int* in_sizes, int n_in,
                              void* d_out, int out_size) {
    const float* x   = (const float*)d_in[0];
    const float* n1g = (const float*)d_in[1];
    const float* n1b = (const float*)d_in[2];
    const float* wq  = (const float*)d_in[3];
    const float* bq  = (const float*)d_in[4];
    const float* wk  = (const float*)d_in[5];
    const float* bk  = (const float*)d_in[6];
    const float* wv  = (const float*)d_in[7];
    const float* bv  = (const float*)d_in[8];
    const float* dqw = (const float*)d_in[9];
    const float* dqb = (const float*)d_in[10];
    const float* dkw = (const float*)d_in[11];
    const float* dkb = (const float*)d_in[12];
    const float* dvw = (const float*)d_in[13];
    const float* dvb = (const float*)d_in[14];
    const float* n2g = (const float*)d_in[15];
    const float* n2b = (const float*)d_in[16];
    const float* f1w = (const float*)d_in[17];
    const float* f1b = (const float*)d_in[18];
    const float* f2w = (const float*)d_in[19];
    const float* f2b = (const float*)d_in[20];
    float* out = (float*)d_out;

    float *pqp, *pkp, *pvp, *pxres, *pbqkv;
    __nv_bfloat16 *pxwh, *pxwl, *pl2h, *pl2l, *phh, *phl, *pwqh, *pwql, *pf1h, *pf1l, *pf2h, *pf2l;
    __nv_bfloat16 *pqh, *pql_, *pkh, *pkl, *pvh, *pvl;
    cudaGetSymbolAddress((void**)&pqp,  g_qp);
    cudaGetSymbolAddress((void**)&pkp,  g_kp);
    cudaGetSymbolAddress((void**)&pvp,  g_vp);
    cudaGetSymbolAddress((void**)&pxres,g_xres);
    cudaGetSymbolAddress((void**)&pbqkv,g_bqkv);
    cudaGetSymbolAddress((void**)&pxwh, g_xwh);
    cudaGetSymbolAddress((void**)&pxwl, g_xwl);
    cudaGetSymbolAddress((void**)&pl2h, g_l2h);
    cudaGetSymbolAddress((void**)&pl2l, g_l2l);
    cudaGetSymbolAddress((void**)&phh,  g_hh);
    cudaGetSymbolAddress((void**)&phl,  g_hl);
    cudaGetSymbolAddress((void**)&pwqh, g_wqh);
    cudaGetSymbolAddress((void**)&pwql, g_wql);
    cudaGetSymbolAddress((void**)&pf1h, g_f1h);
    cudaGetSymbolAddress((void**)&pf1l, g_f1l);
    cudaGetSymbolAddress((void**)&pf2h, g_f2h);
    cudaGetSymbolAddress((void**)&pf2l, g_f2l);
    cudaGetSymbolAddress((void**)&pqh,  g_qh);
    cudaGetSymbolAddress((void**)&pql_, g_ql);
    cudaGetSymbolAddress((void**)&pkh,  g_kh);
    cudaGetSymbolAddress((void**)&pkl,  g_kl);
    cudaGetSymbolAddress((void**)&pvh,  g_vh);
    cudaGetSymbolAddress((void**)&pvl,  g_vl);

    cudaFuncSetAttribute(k_attn, cudaFuncAttributeMaxDynamicSharedMemorySize, AT_SMEM);
    cudaFuncSetAttribute(k_tgemm<0>, cudaFuncAttributeMaxDynamicSharedMemorySize, TG_SMEM);
    cudaFuncSetAttribute(k_tgemm<1>, cudaFuncAttributeMaxDynamicSharedMemorySize, TG_SMEM);
    cudaFuncSetAttribute(k_tgemm<2>, cudaFuncAttributeMaxDynamicSharedMemorySize, TG_SMEM);

    k_prep1<<<(3*96*96 + 255)/256, 256>>>(wq, bq, wk, bk, wv, bv);
    k_prep2<<<(HIDD*96 + 255)/256, 256>>>(f1w, f2w);
    k_ln1<<<NTOK/64, 256>>>(x, n1g, n1b);

    // qkv: D = xw @ wqkv^T (+bias), split to 3 fp32 buffers
    dim3 gq(NTOK/128, 3);
    k_tgemm<0><<<gq, 256, TG_SMEM>>>(pxwh, pxwl, pwqh, pwql, pbqkv, 96,
                                     pqp, pkp, pvp, nullptr, nullptr, nullptr, nullptr);

    // depthwise -> bf16 hi/lo planes
    dim3 gdw(NW, 3);
    k_dw<<<gdw, 392>>>(pqp, dqw, dqb, pqh, pql_);
    k_dw<<<gdw, 392>>>(pkp, dkw, dkb, pkh, pkl);
    k_dw<<<gdw, 392>>>(pvp, dvw, dvb, pvh, pvl);

    // tensor-core fused attention
    k_attn<<<NW, 256, AT_SMEM>>>(pqh, pql_, pkh, pkl, pvh, pvl);

    k_resln2<<<NTOK/32, 256>>>(x, n2g, n2b);

    // MLP1: GELU(ln2 @ f1w^T + f1b) -> bf16 hi/lo planes
    dim3 g2(NTOK/128, HIDD/96);
    k_tgemm<1><<<g2, 256, TG_SMEM>>>(pl2h, pl2l, pf1h, pf1l, f1b, 96,
                                     nullptr, nullptr, nullptr, phh, phl, nullptr, nullptr);
    // MLP2: out^T = (h @ f2w^T + f2b + xres)
    dim3 g3(NTOK/128, 1);
    k_tgemm<2><<<g3, 256, TG_SMEM>>>(phh, phl, pf2h, pf2l, f2b, HIDD,
                                     nullptr, nullptr, nullptr, nullptr, nullptr, pxres, out);
}